// round 2
// baseline (speedup 1.0000x reference)
#include <cuda_runtime.h>
#include <math.h>

#define NN  50000
#define EE  1600000
#define ELE 200000

// ---------------- scratch (device globals; no allocation) ----------------
__device__ float g_xw[NN * 128];   // x@Wc1, later reused for h@Wc2
__device__ float g_h [NN * 128];   // relu layer-1 output
__device__ float g_z [NN * 64];    // layer-2 output
__device__ float g_uv[NN * 128];   // [u | v] per node
__device__ float g_dinv[NN];
__device__ int   g_deg[NN];
__device__ int   g_rowptr[NN + 1];
__device__ int   g_cursor[NN];
__device__ int   g_col[EE];
__device__ float g_wuv[64 * 128];

// ---------------- CSR build ----------------
__global__ void hist_kernel(const int* __restrict__ dst, int E) {
    int i = blockIdx.x * blockDim.x + threadIdx.x;
    if (i < E) atomicAdd(&g_deg[dst[i]], 1);
}

__global__ void dinv_kernel(int n) {
    int i = blockIdx.x * blockDim.x + threadIdx.x;
    if (i < n) g_dinv[i] = rsqrtf((float)g_deg[i] + 1.0f);
}

// single-block scan over g_deg -> g_rowptr (exclusive), g_cursor copy
__global__ void scan_kernel(int n) {
    __shared__ int sm[1024];
    __shared__ int carry_s;
    int t = threadIdx.x;
    if (t == 0) carry_s = 0;
    __syncthreads();
    for (int base = 0; base < n; base += 1024) {
        int v = (base + t < n) ? g_deg[base + t] : 0;
        sm[t] = v;
        __syncthreads();
        for (int off = 1; off < 1024; off <<= 1) {
            int add = (t >= off) ? sm[t - off] : 0;
            __syncthreads();
            if (t >= off) sm[t] += add;
            __syncthreads();
        }
        int incl = sm[t];
        int c = carry_s;
        if (base + t < n) {
            int excl = c + incl - v;
            g_rowptr[base + t] = excl;
            g_cursor[base + t] = excl;
        }
        __syncthreads();
        if (t == 0) carry_s = c + sm[1023];
        __syncthreads();
    }
    if (t == 0) g_rowptr[n] = carry_s;
}

__global__ void fill_kernel(const int* __restrict__ src,
                            const int* __restrict__ dst, int E) {
    int i = blockIdx.x * blockDim.x + threadIdx.x;
    if (i < E) {
        int d = dst[i];
        int pos = atomicAdd(&g_cursor[d], 1);
        g_col[pos] = src[i];
    }
}

// ---------------- SGEMM: C[M,N] = A[M,K] @ B[K,N] ----------------
// BM=64, BN=64, BK=16, 256 threads, 4x4 per thread. N,K multiples of 16/64.
__global__ __launch_bounds__(256)
void sgemm_kernel(const float* __restrict__ A, const float* __restrict__ B,
                  float* __restrict__ C, int M, int N, int K) {
    __shared__ float As[16][64];
    __shared__ float Bs[16][64];
    int t  = threadIdx.x;
    int bm = blockIdx.y * 64;
    int bn = blockIdx.x * 64;
    int tx = t & 15, ty = t >> 4;
    int ar = t >> 2;           // 0..63  A row within tile
    int ac = (t & 3) * 4;      // 0..12  A col (k) within tile
    int br = t >> 4;           // 0..15  B k-row
    int bc = (t & 15) * 4;     // B col within tile

    float acc[4][4] = {};
    for (int k0 = 0; k0 < K; k0 += 16) {
        float4 av = make_float4(0.f, 0.f, 0.f, 0.f);
        int arow = bm + ar;
        if (arow < M) av = *(const float4*)&A[(size_t)arow * K + k0 + ac];
        As[ac + 0][ar] = av.x;
        As[ac + 1][ar] = av.y;
        As[ac + 2][ar] = av.z;
        As[ac + 3][ar] = av.w;
        float4 bv = *(const float4*)&B[(size_t)(k0 + br) * N + bn + bc];
        *(float4*)&Bs[br][bc] = bv;
        __syncthreads();
#pragma unroll
        for (int k = 0; k < 16; k++) {
            float4 a = *(const float4*)&As[k][ty * 4];
            float4 b = *(const float4*)&Bs[k][tx * 4];
            acc[0][0] = fmaf(a.x, b.x, acc[0][0]);
            acc[0][1] = fmaf(a.x, b.y, acc[0][1]);
            acc[0][2] = fmaf(a.x, b.z, acc[0][2]);
            acc[0][3] = fmaf(a.x, b.w, acc[0][3]);
            acc[1][0] = fmaf(a.y, b.x, acc[1][0]);
            acc[1][1] = fmaf(a.y, b.y, acc[1][1]);
            acc[1][2] = fmaf(a.y, b.z, acc[1][2]);
            acc[1][3] = fmaf(a.y, b.w, acc[1][3]);
            acc[2][0] = fmaf(a.z, b.x, acc[2][0]);
            acc[2][1] = fmaf(a.z, b.y, acc[2][1]);
            acc[2][2] = fmaf(a.z, b.z, acc[2][2]);
            acc[2][3] = fmaf(a.z, b.w, acc[2][3]);
            acc[3][0] = fmaf(a.w, b.x, acc[3][0]);
            acc[3][1] = fmaf(a.w, b.y, acc[3][1]);
            acc[3][2] = fmaf(a.w, b.z, acc[3][2]);
            acc[3][3] = fmaf(a.w, b.w, acc[3][3]);
        }
        __syncthreads();
    }
    int row0 = bm + ty * 4;
#pragma unroll
    for (int i = 0; i < 4; i++) {
        int row = row0 + i;
        if (row < M) {
            *(float4*)&C[(size_t)row * N + bn + tx * 4] =
                make_float4(acc[i][0], acc[i][1], acc[i][2], acc[i][3]);
        }
    }
}

// ---------------- GCN aggregation: warp per node, CSR gather ----------------
template <bool RELU>
__global__ void agg128_kernel(const float* __restrict__ xw,
                              float* __restrict__ out,
                              const float* __restrict__ bias) {
    int node = (blockIdx.x * blockDim.x + threadIdx.x) >> 5;
    int lane = threadIdx.x & 31;
    if (node >= NN) return;
    float di  = g_dinv[node];
    int   beg = g_rowptr[node], end = g_rowptr[node + 1];
    float4 acc = make_float4(0.f, 0.f, 0.f, 0.f);
    for (int base = beg; base < end; base += 32) {
        int m = end - base; if (m > 32) m = 32;
        int s = 0; float ds = 0.f;
        if (lane < m) { s = g_col[base + lane]; ds = g_dinv[s]; }
        for (int i = 0; i < m; i++) {
            int   si = __shfl_sync(0xffffffffu, s, i);
            float w  = __shfl_sync(0xffffffffu, ds, i);
            float4 xv = *(const float4*)(xw + (size_t)si * 128 + lane * 4);
            acc.x = fmaf(w, xv.x, acc.x);
            acc.y = fmaf(w, xv.y, acc.y);
            acc.z = fmaf(w, xv.z, acc.z);
            acc.w = fmaf(w, xv.w, acc.w);
        }
    }
    float4 sv = *(const float4*)(xw + (size_t)node * 128 + lane * 4);
    float4 b  = *(const float4*)(bias + lane * 4);
    float  d2 = di * di;
    float4 r;
    r.x = di * acc.x + d2 * sv.x + b.x;
    r.y = di * acc.y + d2 * sv.y + b.y;
    r.z = di * acc.z + d2 * sv.z + b.z;
    r.w = di * acc.w + d2 * sv.w + b.w;
    if (RELU) {
        r.x = fmaxf(r.x, 0.f); r.y = fmaxf(r.y, 0.f);
        r.z = fmaxf(r.z, 0.f); r.w = fmaxf(r.w, 0.f);
    }
    *(float4*)(out + (size_t)node * 128 + lane * 4) = r;
}

template <bool RELU>
__global__ void agg64_kernel(const float* __restrict__ xw,
                             float* __restrict__ out,
                             const float* __restrict__ bias) {
    int node = (blockIdx.x * blockDim.x + threadIdx.x) >> 5;
    int lane = threadIdx.x & 31;
    if (node >= NN) return;
    float di  = g_dinv[node];
    int   beg = g_rowptr[node], end = g_rowptr[node + 1];
    float2 acc = make_float2(0.f, 0.f);
    for (int base = beg; base < end; base += 32) {
        int m = end - base; if (m > 32) m = 32;
        int s = 0; float ds = 0.f;
        if (lane < m) { s = g_col[base + lane]; ds = g_dinv[s]; }
        for (int i = 0; i < m; i++) {
            int   si = __shfl_sync(0xffffffffu, s, i);
            float w  = __shfl_sync(0xffffffffu, ds, i);
            float2 xv = *(const float2*)(xw + (size_t)si * 64 + lane * 2);
            acc.x = fmaf(w, xv.x, acc.x);
            acc.y = fmaf(w, xv.y, acc.y);
        }
    }
    float2 sv = *(const float2*)(xw + (size_t)node * 64 + lane * 2);
    float2 b  = *(const float2*)(bias + lane * 2);
    float  d2 = di * di;
    float2 r;
    r.x = di * acc.x + d2 * sv.x + b.x;
    r.y = di * acc.y + d2 * sv.y + b.y;
    if (RELU) { r.x = fmaxf(r.x, 0.f); r.y = fmaxf(r.y, 0.f); }
    *(float2*)(out + (size_t)node * 64 + lane * 2) = r;
}

// ---------------- pack W1 into [64,128] = [W1_top | W1_bot] ----------------
__global__ void build_wuv_kernel(const float* __restrict__ W1) {
    int k = blockIdx.x;    // 0..63
    int j = threadIdx.x;   // 0..127
    g_wuv[k * 128 + j] = (j < 64) ? W1[k * 64 + j] : W1[(64 + k) * 64 + (j - 64)];
}

// ---------------- decode: warp per label edge ----------------
__global__ void decode_kernel(const float* __restrict__ uv,
                              const int* __restrict__ eli,
                              const float* __restrict__ b1,
                              const float* __restrict__ W2,
                              const float* __restrict__ b2,
                              float* __restrict__ out, int EL) {
    int e    = (blockIdx.x * blockDim.x + threadIdx.x) >> 5;
    int lane = threadIdx.x & 31;
    if (e >= EL) return;
    int s = eli[e];
    int d = eli[EL + e];
    const float2* ps = (const float2*)(uv + (size_t)s * 128);
    const float2* pd = (const float2*)(uv + (size_t)d * 128);
    float2 u_s = ps[lane];       // u[s], j = 2*lane
    float2 v_s = ps[32 + lane];  // v[s]
    float2 u_d = pd[lane];
    float2 v_d = pd[32 + lane];
    float2 bb = ((const float2*)b1)[lane];
    float2 ww = ((const float2*)W2)[lane];
    float sum = 0.f, h;
    h = u_s.x + v_d.x + bb.x; sum = fmaf(fmaxf(h, 0.f), ww.x, sum);
    h = u_s.y + v_d.y + bb.y; sum = fmaf(fmaxf(h, 0.f), ww.y, sum);
    h = u_d.x + v_s.x + bb.x; sum = fmaf(fmaxf(h, 0.f), ww.x, sum);
    h = u_d.y + v_s.y + bb.y; sum = fmaf(fmaxf(h, 0.f), ww.y, sum);
#pragma unroll
    for (int o = 16; o; o >>= 1) sum += __shfl_xor_sync(0xffffffffu, sum, o);
    if (lane == 0) {
        float val = 0.5f * sum + b2[0];
        out[e]      = -val;
        out[EL + e] =  val;
    }
}

// ---------------- launch ----------------
extern "C" void kernel_launch(void* const* d_in, const int* in_sizes, int n_in,
                              void* d_out, int out_size) {
    const float* x   = (const float*)d_in[0];
    const int*   ei  = (const int*)d_in[1];
    const int*   eli = (const int*)d_in[2];
    const float* Wc1 = (const float*)d_in[3];
    const float* bc1 = (const float*)d_in[4];
    const float* Wc2 = (const float*)d_in[5];
    const float* bc2 = (const float*)d_in[6];
    const float* W1  = (const float*)d_in[7];
    const float* b1  = (const float*)d_in[8];
    const float* W2  = (const float*)d_in[9];
    const float* b2  = (const float*)d_in[10];
    float* out = (float*)d_out;

    int E  = in_sizes[1] / 2;
    int EL = in_sizes[2] / 2;

    void *p_xw, *p_h, *p_z, *p_uv, *p_deg, *p_wuv;
    cudaGetSymbolAddress(&p_xw,  g_xw);
    cudaGetSymbolAddress(&p_h,   g_h);
    cudaGetSymbolAddress(&p_z,   g_z);
    cudaGetSymbolAddress(&p_uv,  g_uv);
    cudaGetSymbolAddress(&p_deg, g_deg);
    cudaGetSymbolAddress(&p_wuv, g_wuv);

    // ---- CSR + degrees ----
    cudaMemsetAsync(p_deg, 0, NN * sizeof(int));
    hist_kernel<<<(E + 255) / 256, 256>>>(ei + E, E);
    dinv_kernel<<<(NN + 255) / 256, 256>>>(NN);
    scan_kernel<<<1, 1024>>>(NN);
    fill_kernel<<<(E + 255) / 256, 256>>>(ei, ei + E, E);

    // ---- layer 1: xw = x @ Wc1 ; h = relu(agg) ----
    sgemm_kernel<<<dim3(2, (NN + 63) / 64), 256>>>(x, Wc1, (float*)p_xw, NN, 128, 128);
    agg128_kernel<true><<<(NN + 7) / 8, 256>>>((const float*)p_xw, (float*)p_h, bc1);

    // ---- layer 2: hw = h @ Wc2 (reuse g_xw) ; z = agg ----
    sgemm_kernel<<<dim3(1, (NN + 63) / 64), 256>>>((const float*)p_h, Wc2, (float*)p_xw, NN, 64, 128);
    agg64_kernel<false><<<(NN + 7) / 8, 256>>>((const float*)p_xw, (float*)p_z, bc2);

    // ---- decode precompute: uv = z @ [W1_top | W1_bot] ----
    build_wuv_kernel<<<64, 128>>>(W1);
    sgemm_kernel<<<dim3(2, (NN + 63) / 64), 256>>>((const float*)p_z, (const float*)p_wuv,
                                                   (float*)p_uv, NN, 128, 64);

    // ---- decode per label edge ----
    decode_kernel<<<(EL * 32 + 255) / 256, 256>>>((const float*)p_uv, eli, b1, W2, b2, out, EL);
}

// round 6
// speedup vs baseline: 1.2491x; 1.2491x over previous
#include <cuda_runtime.h>
#include <math.h>

#define NN  50000
#define EE  1600000
#define ELE 200000
#define NB  ((NN + 255) / 256)   // 196 scan blocks

// ---------------- scratch (device globals; no allocation) ----------------
__device__ float g_xw[NN * 128];   // x@Wc1, later reused for h@Wc2
__device__ float g_h [NN * 128];   // relu layer-1 output
__device__ float g_z [NN * 64];    // layer-2 output
__device__ float g_uv[NN * 128];   // [u | v] per node
__device__ float g_dinv[NN];
__device__ int   g_deg[NN];
__device__ int   g_rowptr[NN + 1];
__device__ int   g_cursor[NN];
__device__ int   g_col[EE];
__device__ int   g_partial[256];
__device__ float g_wuv[64 * 128];

// ---------------- CSR build ----------------
__global__ void hist_kernel(const int* __restrict__ dst, int E) {
    int i = blockIdx.x * blockDim.x + threadIdx.x;
    if (i < E) atomicAdd(&g_deg[dst[i]], 1);
}

// phase 1: per-block sums of g_deg
__global__ void scan_partial_kernel() {
    __shared__ int ws[8];
    int i = blockIdx.x * 256 + threadIdx.x;
    int t = threadIdx.x;
    int v = (i < NN) ? g_deg[i] : 0;
#pragma unroll
    for (int o = 16; o; o >>= 1) v += __shfl_xor_sync(0xffffffffu, v, o);
    if ((t & 31) == 0) ws[t >> 5] = v;
    __syncthreads();
    if (t < 8) {
        int s = ws[t];
#pragma unroll
        for (int o = 4; o; o >>= 1) s += __shfl_xor_sync(0xffu, s, o);
        if (t == 0) g_partial[blockIdx.x] = s;
    }
}

// phase 2: exclusive scan of NB (<=256) partials; also seal rowptr[NN]
__global__ void scan_offsets_kernel(int E) {
    __shared__ int sm[256];
    int t = threadIdx.x;
    int v = (t < NB) ? g_partial[t] : 0;
    sm[t] = v;
    __syncthreads();
#pragma unroll
    for (int off = 1; off < 256; off <<= 1) {
        int a = (t >= off) ? sm[t - off] : 0;
        __syncthreads();
        sm[t] += a;
        __syncthreads();
    }
    if (t < NB) g_partial[t] = sm[t] - v;   // exclusive
    if (t == 0) g_rowptr[NN] = E;
}

// phase 3: local scan + offset -> rowptr/cursor; fused dinv
__global__ void scan_final_kernel() {
    __shared__ int sm[256];
    int i = blockIdx.x * 256 + threadIdx.x;
    int t = threadIdx.x;
    int v = (i < NN) ? g_deg[i] : 0;
    sm[t] = v;
    __syncthreads();
#pragma unroll
    for (int off = 1; off < 256; off <<= 1) {
        int a = (t >= off) ? sm[t - off] : 0;
        __syncthreads();
        sm[t] += a;
        __syncthreads();
    }
    if (i < NN) {
        int excl = g_partial[blockIdx.x] + sm[t] - v;
        g_rowptr[i] = excl;
        g_cursor[i] = excl;
        g_dinv[i]   = rsqrtf((float)v + 1.0f);
    }
}

__global__ void fill_kernel(const int* __restrict__ src,
                            const int* __restrict__ dst, int E) {
    int i = blockIdx.x * blockDim.x + threadIdx.x;
    if (i < E) {
        int d = dst[i];
        int pos = atomicAdd(&g_cursor[d], 1);
        g_col[pos] = src[i];
    }
}

// ---------------- SGEMM: C[M,N] = A[M,K] @ B[K,N] ----------------
// BM=128, BN=64, BK=16, 256 threads, 8x4 per thread. N mult of 64, K mult of 16.
// Launch with grid.x = N/64. As padded to 132 floats/row: 528 B stride stays
// 16B-aligned for LDS.128; 132 mod 32 = 4 keeps transposed stores cheap.
__global__ __launch_bounds__(256)
void sgemm_kernel(const float* __restrict__ A, const float* __restrict__ B,
                  float* __restrict__ C, int M, int N, int K) {
    __shared__ float As[16][132];
    __shared__ float Bs[16][64];
    int t  = threadIdx.x;
    int bm = blockIdx.y * 128;
    int bn = blockIdx.x * 64;
    int ar0 = t >> 2;            // A row (first of two), 0..63
    int akc = (t & 3) * 4;       // A k-col
    int br  = t >> 4;            // B k-row
    int bnc = (t & 15) * 4;      // B n-col
    int ty = t >> 4, tx = t & 15;

    float acc[8][4] = {};
    for (int k0 = 0; k0 < K; k0 += 16) {
#pragma unroll
        for (int h = 0; h < 2; h++) {
            int r = ar0 + h * 64;
            float4 av = make_float4(0.f, 0.f, 0.f, 0.f);
            if (bm + r < M) av = *(const float4*)&A[(size_t)(bm + r) * K + k0 + akc];
            As[akc + 0][r] = av.x;
            As[akc + 1][r] = av.y;
            As[akc + 2][r] = av.z;
            As[akc + 3][r] = av.w;
        }
        float4 bv = *(const float4*)&B[(size_t)(k0 + br) * N + bn + bnc];
        *(float4*)&Bs[br][bnc] = bv;
        __syncthreads();
#pragma unroll
        for (int k = 0; k < 16; k++) {
            float4 a0 = *(const float4*)&As[k][ty * 8];
            float4 a1 = *(const float4*)&As[k][ty * 8 + 4];
            float4 b  = *(const float4*)&Bs[k][tx * 4];
            float am[8] = {a0.x, a0.y, a0.z, a0.w, a1.x, a1.y, a1.z, a1.w};
#pragma unroll
            for (int i = 0; i < 8; i++) {
                acc[i][0] = fmaf(am[i], b.x, acc[i][0]);
                acc[i][1] = fmaf(am[i], b.y, acc[i][1]);
                acc[i][2] = fmaf(am[i], b.z, acc[i][2]);
                acc[i][3] = fmaf(am[i], b.w, acc[i][3]);
            }
        }
        __syncthreads();
    }
    int row0 = bm + ty * 8;
#pragma unroll
    for (int i = 0; i < 8; i++) {
        int row = row0 + i;
        if (row < M) {
            *(float4*)&C[(size_t)row * N + bn + tx * 4] =
                make_float4(acc[i][0], acc[i][1], acc[i][2], acc[i][3]);
        }
    }
}

// ---------------- GCN aggregation: warp per node, CSR gather ----------------
template <bool RELU>
__global__ void agg128_kernel(const float* __restrict__ xw,
                              float* __restrict__ out,
                              const float* __restrict__ bias) {
    int node = (blockIdx.x * blockDim.x + threadIdx.x) >> 5;
    int lane = threadIdx.x & 31;
    if (node >= NN) return;
    float di  = g_dinv[node];
    int   beg = g_rowptr[node], end = g_rowptr[node + 1];
    float4 acc = make_float4(0.f, 0.f, 0.f, 0.f);
    for (int base = beg; base < end; base += 32) {
        int m = end - base; if (m > 32) m = 32;
        int s = 0; float ds = 0.f;
        if (lane < m) { s = g_col[base + lane]; ds = g_dinv[s]; }
        int i = 0;
        for (; i + 4 <= m; i += 4) {
            int   s0 = __shfl_sync(0xffffffffu, s, i);
            int   s1 = __shfl_sync(0xffffffffu, s, i + 1);
            int   s2 = __shfl_sync(0xffffffffu, s, i + 2);
            int   s3 = __shfl_sync(0xffffffffu, s, i + 3);
            float w0 = __shfl_sync(0xffffffffu, ds, i);
            float w1 = __shfl_sync(0xffffffffu, ds, i + 1);
            float w2 = __shfl_sync(0xffffffffu, ds, i + 2);
            float w3 = __shfl_sync(0xffffffffu, ds, i + 3);
            float4 x0 = *(const float4*)(xw + (size_t)s0 * 128 + lane * 4);
            float4 x1 = *(const float4*)(xw + (size_t)s1 * 128 + lane * 4);
            float4 x2 = *(const float4*)(xw + (size_t)s2 * 128 + lane * 4);
            float4 x3 = *(const float4*)(xw + (size_t)s3 * 128 + lane * 4);
            acc.x = fmaf(w0, x0.x, acc.x); acc.y = fmaf(w0, x0.y, acc.y);
            acc.z = fmaf(w0, x0.z, acc.z); acc.w = fmaf(w0, x0.w, acc.w);
            acc.x = fmaf(w1, x1.x, acc.x); acc.y = fmaf(w1, x1.y, acc.y);
            acc.z = fmaf(w1, x1.z, acc.z); acc.w = fmaf(w1, x1.w, acc.w);
            acc.x = fmaf(w2, x2.x, acc.x); acc.y = fmaf(w2, x2.y, acc.y);
            acc.z = fmaf(w2, x2.z, acc.z); acc.w = fmaf(w2, x2.w, acc.w);
            acc.x = fmaf(w3, x3.x, acc.x); acc.y = fmaf(w3, x3.y, acc.y);
            acc.z = fmaf(w3, x3.z, acc.z); acc.w = fmaf(w3, x3.w, acc.w);
        }
        for (; i < m; i++) {
            int   si = __shfl_sync(0xffffffffu, s, i);
            float w  = __shfl_sync(0xffffffffu, ds, i);
            float4 xv = *(const float4*)(xw + (size_t)si * 128 + lane * 4);
            acc.x = fmaf(w, xv.x, acc.x); acc.y = fmaf(w, xv.y, acc.y);
            acc.z = fmaf(w, xv.z, acc.z); acc.w = fmaf(w, xv.w, acc.w);
        }
    }
    float4 sv = *(const float4*)(xw + (size_t)node * 128 + lane * 4);
    float4 b  = *(const float4*)(bias + lane * 4);
    float  d2 = di * di;
    float4 r;
    r.x = di * acc.x + d2 * sv.x + b.x;
    r.y = di * acc.y + d2 * sv.y + b.y;
    r.z = di * acc.z + d2 * sv.z + b.z;
    r.w = di * acc.w + d2 * sv.w + b.w;
    if (RELU) {
        r.x = fmaxf(r.x, 0.f); r.y = fmaxf(r.y, 0.f);
        r.z = fmaxf(r.z, 0.f); r.w = fmaxf(r.w, 0.f);
    }
    *(float4*)(out + (size_t)node * 128 + lane * 4) = r;
}

template <bool RELU>
__global__ void agg64_kernel(const float* __restrict__ xw,
                             float* __restrict__ out,
                             const float* __restrict__ bias) {
    int node = (blockIdx.x * blockDim.x + threadIdx.x) >> 5;
    int lane = threadIdx.x & 31;
    if (node >= NN) return;
    float di  = g_dinv[node];
    int   beg = g_rowptr[node], end = g_rowptr[node + 1];
    float2 acc = make_float2(0.f, 0.f);
    for (int base = beg; base < end; base += 32) {
        int m = end - base; if (m > 32) m = 32;
        int s = 0; float ds = 0.f;
        if (lane < m) { s = g_col[base + lane]; ds = g_dinv[s]; }
        int i = 0;
        for (; i + 4 <= m; i += 4) {
            int   s0 = __shfl_sync(0xffffffffu, s, i);
            int   s1 = __shfl_sync(0xffffffffu, s, i + 1);
            int   s2 = __shfl_sync(0xffffffffu, s, i + 2);
            int   s3 = __shfl_sync(0xffffffffu, s, i + 3);
            float w0 = __shfl_sync(0xffffffffu, ds, i);
            float w1 = __shfl_sync(0xffffffffu, ds, i + 1);
            float w2 = __shfl_sync(0xffffffffu, ds, i + 2);
            float w3 = __shfl_sync(0xffffffffu, ds, i + 3);
            float2 x0 = *(const float2*)(xw + (size_t)s0 * 64 + lane * 2);
            float2 x1 = *(const float2*)(xw + (size_t)s1 * 64 + lane * 2);
            float2 x2 = *(const float2*)(xw + (size_t)s2 * 64 + lane * 2);
            float2 x3 = *(const float2*)(xw + (size_t)s3 * 64 + lane * 2);
            acc.x = fmaf(w0, x0.x, acc.x); acc.y = fmaf(w0, x0.y, acc.y);
            acc.x = fmaf(w1, x1.x, acc.x); acc.y = fmaf(w1, x1.y, acc.y);
            acc.x = fmaf(w2, x2.x, acc.x); acc.y = fmaf(w2, x2.y, acc.y);
            acc.x = fmaf(w3, x3.x, acc.x); acc.y = fmaf(w3, x3.y, acc.y);
        }
        for (; i < m; i++) {
            int   si = __shfl_sync(0xffffffffu, s, i);
            float w  = __shfl_sync(0xffffffffu, ds, i);
            float2 xv = *(const float2*)(xw + (size_t)si * 64 + lane * 2);
            acc.x = fmaf(w, xv.x, acc.x); acc.y = fmaf(w, xv.y, acc.y);
        }
    }
    float2 sv = *(const float2*)(xw + (size_t)node * 64 + lane * 2);
    float2 b  = *(const float2*)(bias + lane * 2);
    float  d2 = di * di;
    float2 r;
    r.x = di * acc.x + d2 * sv.x + b.x;
    r.y = di * acc.y + d2 * sv.y + b.y;
    if (RELU) { r.x = fmaxf(r.x, 0.f); r.y = fmaxf(r.y, 0.f); }
    *(float2*)(out + (size_t)node * 64 + lane * 2) = r;
}

// ---------------- pack W1 into [64,128] = [W1_top | W1_bot] ----------------
__global__ void build_wuv_kernel(const float* __restrict__ W1) {
    int k = blockIdx.x;    // 0..63
    int j = threadIdx.x;   // 0..127
    g_wuv[k * 128 + j] = (j < 64) ? W1[k * 64 + j] : W1[(64 + k) * 64 + (j - 64)];
}

// ---------------- decode: warp per label edge ----------------
__global__ void decode_kernel(const float* __restrict__ uv,
                              const int* __restrict__ eli,
                              const float* __restrict__ b1,
                              const float* __restrict__ W2,
                              const float* __restrict__ b2,
                              float* __restrict__ out, int EL) {
    int e    = (blockIdx.x * blockDim.x + threadIdx.x) >> 5;
    int lane = threadIdx.x & 31;
    if (e >= EL) return;
    int s = eli[e];
    int d = eli[EL + e];
    const float2* ps = (const float2*)(uv + (size_t)s * 128);
    const float2* pd = (const float2*)(uv + (size_t)d * 128);
    float2 u_s = ps[lane];       // u[s], j = 2*lane
    float2 v_s = ps[32 + lane];  // v[s]
    float2 u_d = pd[lane];
    float2 v_d = pd[32 + lane];
    float2 bb = ((const float2*)b1)[lane];
    float2 ww = ((const float2*)W2)[lane];
    float sum = 0.f, h;
    h = u_s.x + v_d.x + bb.x; sum = fmaf(fmaxf(h, 0.f), ww.x, sum);
    h = u_s.y + v_d.y + bb.y; sum = fmaf(fmaxf(h, 0.f), ww.y, sum);
    h = u_d.x + v_s.x + bb.x; sum = fmaf(fmaxf(h, 0.f), ww.x, sum);
    h = u_d.y + v_s.y + bb.y; sum = fmaf(fmaxf(h, 0.f), ww.y, sum);
#pragma unroll
    for (int o = 16; o; o >>= 1) sum += __shfl_xor_sync(0xffffffffu, sum, o);
    if (lane == 0) {
        float val = 0.5f * sum + b2[0];
        out[e]      = -val;
        out[EL + e] =  val;
    }
}

// ---------------- launch ----------------
extern "C" void kernel_launch(void* const* d_in, const int* in_sizes, int n_in,
                              void* d_out, int out_size) {
    const float* x   = (const float*)d_in[0];
    const int*   ei  = (const int*)d_in[1];
    const int*   eli = (const int*)d_in[2];
    const float* Wc1 = (const float*)d_in[3];
    const float* bc1 = (const float*)d_in[4];
    const float* Wc2 = (const float*)d_in[5];
    const float* bc2 = (const float*)d_in[6];
    const float* W1  = (const float*)d_in[7];
    const float* b1  = (const float*)d_in[8];
    const float* W2  = (const float*)d_in[9];
    const float* b2  = (const float*)d_in[10];
    float* out = (float*)d_out;

    int E  = in_sizes[1] / 2;
    int EL = in_sizes[2] / 2;

    void *p_xw, *p_h, *p_z, *p_uv, *p_deg, *p_wuv;
    cudaGetSymbolAddress(&p_xw,  g_xw);
    cudaGetSymbolAddress(&p_h,   g_h);
    cudaGetSymbolAddress(&p_z,   g_z);
    cudaGetSymbolAddress(&p_uv,  g_uv);
    cudaGetSymbolAddress(&p_deg, g_deg);
    cudaGetSymbolAddress(&p_wuv, g_wuv);

    // ---- CSR + degrees ----
    cudaMemsetAsync(p_deg, 0, NN * sizeof(int));
    hist_kernel<<<(E + 255) / 256, 256>>>(ei + E, E);
    scan_partial_kernel<<<NB, 256>>>();
    scan_offsets_kernel<<<1, 256>>>(E);
    scan_final_kernel<<<NB, 256>>>();
    fill_kernel<<<(E + 255) / 256, 256>>>(ei, ei + E, E);

    // ---- layer 1: xw = x @ Wc1 ; h = relu(agg) ----  (N=128 -> grid.x=2)
    sgemm_kernel<<<dim3(2, (NN + 127) / 128), 256>>>(x, Wc1, (float*)p_xw, NN, 128, 128);
    agg128_kernel<true><<<(NN + 7) / 8, 256>>>((const float*)p_xw, (float*)p_h, bc1);

    // ---- layer 2: hw = h @ Wc2 (reuse g_xw) ; z = agg ----  (N=64 -> grid.x=1)
    sgemm_kernel<<<dim3(1, (NN + 127) / 128), 256>>>((const float*)p_h, Wc2, (float*)p_xw, NN, 64, 128);
    agg64_kernel<false><<<(NN + 7) / 8, 256>>>((const float*)p_xw, (float*)p_z, bc2);

    // ---- decode precompute: uv = z @ [W1_top | W1_bot] ----  (N=128 -> grid.x=2)
    build_wuv_kernel<<<64, 128>>>(W1);
    sgemm_kernel<<<dim3(2, (NN + 127) / 128), 256>>>((const float*)p_z, (const float*)p_wuv,
                                                     (float*)p_uv, NN, 128, 64);

    // ---- decode per label edge ----
    decode_kernel<<<(EL * 32 + 255) / 256, 256>>>((const float*)p_uv, eli, b1, W2, b2, out, EL);
}

// round 7
// speedup vs baseline: 1.3434x; 1.0755x over previous
#include <cuda_runtime.h>
#include <math.h>

#define NN  50000
#define EE  1600000
#define ELE 200000
#define NB  ((NN + 255) / 256)   // 196 scan blocks

// ---------------- scratch (device globals; no allocation) ----------------
__device__ float g_xw[NN * 128];   // x@Wc1, later reused for h@Wc2
__device__ float g_h [NN * 128];   // relu layer-1 output
__device__ float g_z [NN * 64];    // layer-2 output
__device__ float g_uv[NN * 128];   // [u | v] per node
__device__ float g_dinv[NN];
__device__ int   g_deg[NN];
__device__ int   g_rowptr[NN + 1];
__device__ int   g_cursor[NN];
__device__ int   g_col[EE];
__device__ int   g_partial[256];
__device__ float g_wuv[64 * 128];

// ---------------- CSR build ----------------
__global__ void hist_kernel(const int* __restrict__ dst, int E) {
    int i = blockIdx.x * blockDim.x + threadIdx.x;
    if (i < E) atomicAdd(&g_deg[dst[i]], 1);
}

// phase 1: per-block sums of g_deg
__global__ void scan_partial_kernel() {
    __shared__ int ws[8];
    int i = blockIdx.x * 256 + threadIdx.x;
    int t = threadIdx.x;
    int v = (i < NN) ? g_deg[i] : 0;
#pragma unroll
    for (int o = 16; o; o >>= 1) v += __shfl_xor_sync(0xffffffffu, v, o);
    if ((t & 31) == 0) ws[t >> 5] = v;
    __syncthreads();
    if (t < 8) {
        int s = ws[t];
#pragma unroll
        for (int o = 4; o; o >>= 1) s += __shfl_xor_sync(0xffu, s, o);
        if (t == 0) g_partial[blockIdx.x] = s;
    }
}

// phase 2: exclusive scan of NB (<=256) partials; also seal rowptr[NN]
__global__ void scan_offsets_kernel(int E) {
    __shared__ int sm[256];
    int t = threadIdx.x;
    int v = (t < NB) ? g_partial[t] : 0;
    sm[t] = v;
    __syncthreads();
#pragma unroll
    for (int off = 1; off < 256; off <<= 1) {
        int a = (t >= off) ? sm[t - off] : 0;
        __syncthreads();
        sm[t] += a;
        __syncthreads();
    }
    if (t < NB) g_partial[t] = sm[t] - v;   // exclusive
    if (t == 0) g_rowptr[NN] = E;
}

// phase 3: local scan + offset -> rowptr/cursor; fused dinv
__global__ void scan_final_kernel() {
    __shared__ int sm[256];
    int i = blockIdx.x * 256 + threadIdx.x;
    int t = threadIdx.x;
    int v = (i < NN) ? g_deg[i] : 0;
    sm[t] = v;
    __syncthreads();
#pragma unroll
    for (int off = 1; off < 256; off <<= 1) {
        int a = (t >= off) ? sm[t - off] : 0;
        __syncthreads();
        sm[t] += a;
        __syncthreads();
    }
    if (i < NN) {
        int excl = g_partial[blockIdx.x] + sm[t] - v;
        g_rowptr[i] = excl;
        g_cursor[i] = excl;
        g_dinv[i]   = rsqrtf((float)v + 1.0f);
    }
}

__global__ void fill_kernel(const int* __restrict__ src,
                            const int* __restrict__ dst, int E) {
    int i = blockIdx.x * blockDim.x + threadIdx.x;
    if (i < E) {
        int d = dst[i];
        int pos = atomicAdd(&g_cursor[d], 1);
        g_col[pos] = src[i];
    }
}

// ---------------- SGEMM: C[M,N] = A[M,K] @ B[K,N] ----------------
// BM=128, BN=64, BK=16, 256 threads, 8x4 per thread. Launch grid.x = N/64.
__global__ __launch_bounds__(256)
void sgemm_kernel(const float* __restrict__ A, const float* __restrict__ B,
                  float* __restrict__ C, int M, int N, int K) {
    __shared__ float As[16][132];
    __shared__ float Bs[16][64];
    int t  = threadIdx.x;
    int bm = blockIdx.y * 128;
    int bn = blockIdx.x * 64;
    int ar0 = t >> 2;            // A row (first of two), 0..63
    int akc = (t & 3) * 4;       // A k-col
    int br  = t >> 4;            // B k-row
    int bnc = (t & 15) * 4;      // B n-col
    int ty = t >> 4, tx = t & 15;

    float acc[8][4] = {};
    for (int k0 = 0; k0 < K; k0 += 16) {
#pragma unroll
        for (int h = 0; h < 2; h++) {
            int r = ar0 + h * 64;
            float4 av = make_float4(0.f, 0.f, 0.f, 0.f);
            if (bm + r < M) av = *(const float4*)&A[(size_t)(bm + r) * K + k0 + akc];
            As[akc + 0][r] = av.x;
            As[akc + 1][r] = av.y;
            As[akc + 2][r] = av.z;
            As[akc + 3][r] = av.w;
        }
        float4 bv = *(const float4*)&B[(size_t)(k0 + br) * N + bn + bnc];
        *(float4*)&Bs[br][bnc] = bv;
        __syncthreads();
#pragma unroll
        for (int k = 0; k < 16; k++) {
            float4 a0 = *(const float4*)&As[k][ty * 8];
            float4 a1 = *(const float4*)&As[k][ty * 8 + 4];
            float4 b  = *(const float4*)&Bs[k][tx * 4];
            float am[8] = {a0.x, a0.y, a0.z, a0.w, a1.x, a1.y, a1.z, a1.w};
#pragma unroll
            for (int i = 0; i < 8; i++) {
                acc[i][0] = fmaf(am[i], b.x, acc[i][0]);
                acc[i][1] = fmaf(am[i], b.y, acc[i][1]);
                acc[i][2] = fmaf(am[i], b.z, acc[i][2]);
                acc[i][3] = fmaf(am[i], b.w, acc[i][3]);
            }
        }
        __syncthreads();
    }
    int row0 = bm + ty * 8;
#pragma unroll
    for (int i = 0; i < 8; i++) {
        int row = row0 + i;
        if (row < M) {
            *(float4*)&C[(size_t)row * N + bn + tx * 4] =
                make_float4(acc[i][0], acc[i][1], acc[i][2], acc[i][3]);
        }
    }
}

// ---------------- GCN aggregation: warp per node, CSR gather, MLP=8 --------
template <bool RELU>
__global__ void agg128_kernel(const float* __restrict__ xw,
                              float* __restrict__ out,
                              const float* __restrict__ bias) {
    int node = (blockIdx.x * blockDim.x + threadIdx.x) >> 5;
    int lane = threadIdx.x & 31;
    if (node >= NN) return;
    float di  = g_dinv[node];
    int   beg = g_rowptr[node], end = g_rowptr[node + 1];
    float4 acc = make_float4(0.f, 0.f, 0.f, 0.f);
    for (int base = beg; base < end; base += 32) {
        int m = end - base; if (m > 32) m = 32;
        int s = 0; float ds = 0.f;
        if (lane < m) { s = g_col[base + lane]; ds = g_dinv[s]; }
        int i = 0;
        for (; i + 8 <= m; i += 8) {
            int   si[8]; float w[8]; float4 xv[8];
#pragma unroll
            for (int j = 0; j < 8; j++) {
                si[j] = __shfl_sync(0xffffffffu, s,  i + j);
                w[j]  = __shfl_sync(0xffffffffu, ds, i + j);
            }
#pragma unroll
            for (int j = 0; j < 8; j++)
                xv[j] = *(const float4*)(xw + (size_t)si[j] * 128 + lane * 4);
#pragma unroll
            for (int j = 0; j < 8; j++) {
                acc.x = fmaf(w[j], xv[j].x, acc.x);
                acc.y = fmaf(w[j], xv[j].y, acc.y);
                acc.z = fmaf(w[j], xv[j].z, acc.z);
                acc.w = fmaf(w[j], xv[j].w, acc.w);
            }
        }
        for (; i < m; i++) {
            int   si = __shfl_sync(0xffffffffu, s, i);
            float w  = __shfl_sync(0xffffffffu, ds, i);
            float4 xv = *(const float4*)(xw + (size_t)si * 128 + lane * 4);
            acc.x = fmaf(w, xv.x, acc.x); acc.y = fmaf(w, xv.y, acc.y);
            acc.z = fmaf(w, xv.z, acc.z); acc.w = fmaf(w, xv.w, acc.w);
        }
    }
    float4 sv = *(const float4*)(xw + (size_t)node * 128 + lane * 4);
    float4 b  = *(const float4*)(bias + lane * 4);
    float  d2 = di * di;
    float4 r;
    r.x = di * acc.x + d2 * sv.x + b.x;
    r.y = di * acc.y + d2 * sv.y + b.y;
    r.z = di * acc.z + d2 * sv.z + b.z;
    r.w = di * acc.w + d2 * sv.w + b.w;
    if (RELU) {
        r.x = fmaxf(r.x, 0.f); r.y = fmaxf(r.y, 0.f);
        r.z = fmaxf(r.z, 0.f); r.w = fmaxf(r.w, 0.f);
    }
    *(float4*)(out + (size_t)node * 128 + lane * 4) = r;
}

template <bool RELU>
__global__ void agg64_kernel(const float* __restrict__ xw,
                             float* __restrict__ out,
                             const float* __restrict__ bias) {
    int node = (blockIdx.x * blockDim.x + threadIdx.x) >> 5;
    int lane = threadIdx.x & 31;
    if (node >= NN) return;
    float di  = g_dinv[node];
    int   beg = g_rowptr[node], end = g_rowptr[node + 1];
    float2 acc = make_float2(0.f, 0.f);
    for (int base = beg; base < end; base += 32) {
        int m = end - base; if (m > 32) m = 32;
        int s = 0; float ds = 0.f;
        if (lane < m) { s = g_col[base + lane]; ds = g_dinv[s]; }
        int i = 0;
        for (; i + 8 <= m; i += 8) {
            int   si[8]; float w[8]; float2 xv[8];
#pragma unroll
            for (int j = 0; j < 8; j++) {
                si[j] = __shfl_sync(0xffffffffu, s,  i + j);
                w[j]  = __shfl_sync(0xffffffffu, ds, i + j);
            }
#pragma unroll
            for (int j = 0; j < 8; j++)
                xv[j] = *(const float2*)(xw + (size_t)si[j] * 64 + lane * 2);
#pragma unroll
            for (int j = 0; j < 8; j++) {
                acc.x = fmaf(w[j], xv[j].x, acc.x);
                acc.y = fmaf(w[j], xv[j].y, acc.y);
            }
        }
        for (; i < m; i++) {
            int   si = __shfl_sync(0xffffffffu, s, i);
            float w  = __shfl_sync(0xffffffffu, ds, i);
            float2 xv = *(const float2*)(xw + (size_t)si * 64 + lane * 2);
            acc.x = fmaf(w, xv.x, acc.x); acc.y = fmaf(w, xv.y, acc.y);
        }
    }
    float2 sv = *(const float2*)(xw + (size_t)node * 64 + lane * 2);
    float2 b  = *(const float2*)(bias + lane * 2);
    float  d2 = di * di;
    float2 r;
    r.x = di * acc.x + d2 * sv.x + b.x;
    r.y = di * acc.y + d2 * sv.y + b.y;
    if (RELU) { r.x = fmaxf(r.x, 0.f); r.y = fmaxf(r.y, 0.f); }
    *(float2*)(out + (size_t)node * 64 + lane * 2) = r;
}

// ---------------- pack W1 into [64,128] = [W1_top | W1_bot] ----------------
__global__ void build_wuv_kernel(const float* __restrict__ W1) {
    int k = blockIdx.x;    // 0..63
    int j = threadIdx.x;   // 0..127
    g_wuv[k * 128 + j] = (j < 64) ? W1[k * 64 + j] : W1[(64 + k) * 64 + (j - 64)];
}

// ---------------- decode: warp per label edge ----------------
__global__ void decode_kernel(const float* __restrict__ uv,
                              const int* __restrict__ eli,
                              const float* __restrict__ b1,
                              const float* __restrict__ W2,
                              const float* __restrict__ b2,
                              float* __restrict__ out, int EL) {
    int e    = (blockIdx.x * blockDim.x + threadIdx.x) >> 5;
    int lane = threadIdx.x & 31;
    if (e >= EL) return;
    int s = eli[e];
    int d = eli[EL + e];
    const float2* ps = (const float2*)(uv + (size_t)s * 128);
    const float2* pd = (const float2*)(uv + (size_t)d * 128);
    float2 u_s = ps[lane];       // u[s], j = 2*lane
    float2 v_s = ps[32 + lane];  // v[s]
    float2 u_d = pd[lane];
    float2 v_d = pd[32 + lane];
    float2 bb = ((const float2*)b1)[lane];
    float2 ww = ((const float2*)W2)[lane];
    float sum = 0.f, h;
    h = u_s.x + v_d.x + bb.x; sum = fmaf(fmaxf(h, 0.f), ww.x, sum);
    h = u_s.y + v_d.y + bb.y; sum = fmaf(fmaxf(h, 0.f), ww.y, sum);
    h = u_d.x + v_s.x + bb.x; sum = fmaf(fmaxf(h, 0.f), ww.x, sum);
    h = u_d.y + v_s.y + bb.y; sum = fmaf(fmaxf(h, 0.f), ww.y, sum);
#pragma unroll
    for (int o = 16; o; o >>= 1) sum += __shfl_xor_sync(0xffffffffu, sum, o);
    if (lane == 0) {
        float val = 0.5f * sum + b2[0];
        out[e]      = -val;
        out[EL + e] =  val;
    }
}

// ---------------- launch ----------------
extern "C" void kernel_launch(void* const* d_in, const int* in_sizes, int n_in,
                              void* d_out, int out_size) {
    const float* x   = (const float*)d_in[0];
    const int*   ei  = (const int*)d_in[1];
    const int*   eli = (const int*)d_in[2];
    const float* Wc1 = (const float*)d_in[3];
    const float* bc1 = (const float*)d_in[4];
    const float* Wc2 = (const float*)d_in[5];
    const float* bc2 = (const float*)d_in[6];
    const float* W1  = (const float*)d_in[7];
    const float* b1  = (const float*)d_in[8];
    const float* W2  = (const float*)d_in[9];
    const float* b2  = (const float*)d_in[10];
    float* out = (float*)d_out;

    int E  = in_sizes[1] / 2;
    int EL = in_sizes[2] / 2;

    void *p_xw, *p_h, *p_z, *p_uv, *p_deg, *p_wuv;
    cudaGetSymbolAddress(&p_xw,  g_xw);
    cudaGetSymbolAddress(&p_h,   g_h);
    cudaGetSymbolAddress(&p_z,   g_z);
    cudaGetSymbolAddress(&p_uv,  g_uv);
    cudaGetSymbolAddress(&p_deg, g_deg);
    cudaGetSymbolAddress(&p_wuv, g_wuv);

    // one-time side-stream + events (host-side objects only; no device mem)
    static cudaStream_t s1 = nullptr;
    static cudaEvent_t  evFork = nullptr, evJoin = nullptr;
    if (s1 == nullptr) {
        cudaStreamCreateWithFlags(&s1, cudaStreamNonBlocking);
        cudaEventCreateWithFlags(&evFork, cudaEventDisableTiming);
        cudaEventCreateWithFlags(&evJoin, cudaEventDisableTiming);
    }

    // ---- fork: CSR chain on s1, GEMM1 + wuv pack on main stream ----
    cudaEventRecord(evFork, 0);
    cudaStreamWaitEvent(s1, evFork, 0);

    cudaMemsetAsync(p_deg, 0, NN * sizeof(int), s1);
    hist_kernel<<<(E + 255) / 256, 256, 0, s1>>>(ei + E, E);
    scan_partial_kernel<<<NB, 256, 0, s1>>>();
    scan_offsets_kernel<<<1, 256, 0, s1>>>(E);
    scan_final_kernel<<<NB, 256, 0, s1>>>();
    fill_kernel<<<(E + 255) / 256, 256, 0, s1>>>(ei, ei + E, E);
    cudaEventRecord(evJoin, s1);

    // main stream (concurrent with CSR build): xw = x @ Wc1 ; wuv pack
    sgemm_kernel<<<dim3(2, (NN + 127) / 128), 256>>>(x, Wc1, (float*)p_xw, NN, 128, 128);
    build_wuv_kernel<<<64, 128>>>(W1);

    // ---- join: aggregation needs CSR + dinv + xw ----
    cudaStreamWaitEvent(0, evJoin, 0);

    agg128_kernel<true><<<(NN + 7) / 8, 256>>>((const float*)p_xw, (float*)p_h, bc1);

    // ---- layer 2: hw = h @ Wc2 (reuse g_xw) ; z = agg ----
    sgemm_kernel<<<dim3(1, (NN + 127) / 128), 256>>>((const float*)p_h, Wc2, (float*)p_xw, NN, 64, 128);
    agg64_kernel<false><<<(NN + 7) / 8, 256>>>((const float*)p_xw, (float*)p_z, bc2);

    // ---- decode precompute: uv = z @ [W1_top | W1_bot] ----
    sgemm_kernel<<<dim3(2, (NN + 127) / 128), 256>>>((const float*)p_z, (const float*)p_wuv,
                                                     (float*)p_uv, NN, 128, 64);

    // ---- decode per label edge ----
    decode_kernel<<<(EL * 32 + 255) / 256, 256>>>((const float*)p_uv, eli, b1, W2, b2, out, EL);
}

// round 8
// speedup vs baseline: 1.3942x; 1.0378x over previous
#include <cuda_runtime.h>
#include <cuda_fp16.h>
#include <math.h>

#define NN  50000
#define EE  1600000
#define ELE 200000
#define NB  ((NN + 255) / 256)   // 196 scan blocks

// ---------------- scratch (device globals; no allocation) ----------------
__device__ __half g_xw16[NN * 128];  // fp16 x@Wc1 (reused for h@Wc2)
__device__ float  g_h [NN * 128];    // relu layer-1 output (fp32, GEMM2 A input)
__device__ float  g_z [NN * 64];     // layer-2 output
__device__ float  g_uv[NN * 128];    // [u | v] per node
__device__ float  g_dinv[NN];
__device__ int    g_deg[NN];
__device__ int    g_rowptr[NN + 1];
__device__ int    g_cursor[NN];
__device__ int    g_col[EE];
__device__ int    g_partial[256];
__device__ float  g_wuv[64 * 128];

// ---------------- CSR build ----------------
__global__ void hist_kernel(const int* __restrict__ dst, int E) {
    int i = blockIdx.x * blockDim.x + threadIdx.x;
    if (i < E) atomicAdd(&g_deg[dst[i]], 1);
}

__global__ void scan_partial_kernel() {
    __shared__ int ws[8];
    int i = blockIdx.x * 256 + threadIdx.x;
    int t = threadIdx.x;
    int v = (i < NN) ? g_deg[i] : 0;
#pragma unroll
    for (int o = 16; o; o >>= 1) v += __shfl_xor_sync(0xffffffffu, v, o);
    if ((t & 31) == 0) ws[t >> 5] = v;
    __syncthreads();
    if (t < 8) {
        int s = ws[t];
#pragma unroll
        for (int o = 4; o; o >>= 1) s += __shfl_xor_sync(0xffu, s, o);
        if (t == 0) g_partial[blockIdx.x] = s;
    }
}

__global__ void scan_offsets_kernel(int E) {
    __shared__ int sm[256];
    int t = threadIdx.x;
    int v = (t < NB) ? g_partial[t] : 0;
    sm[t] = v;
    __syncthreads();
#pragma unroll
    for (int off = 1; off < 256; off <<= 1) {
        int a = (t >= off) ? sm[t - off] : 0;
        __syncthreads();
        sm[t] += a;
        __syncthreads();
    }
    if (t < NB) g_partial[t] = sm[t] - v;   // exclusive
    if (t == 0) g_rowptr[NN] = E;
}

__global__ void scan_final_kernel() {
    __shared__ int sm[256];
    int i = blockIdx.x * 256 + threadIdx.x;
    int t = threadIdx.x;
    int v = (i < NN) ? g_deg[i] : 0;
    sm[t] = v;
    __syncthreads();
#pragma unroll
    for (int off = 1; off < 256; off <<= 1) {
        int a = (t >= off) ? sm[t - off] : 0;
        __syncthreads();
        sm[t] += a;
        __syncthreads();
    }
    if (i < NN) {
        int excl = g_partial[blockIdx.x] + sm[t] - v;
        g_rowptr[i] = excl;
        g_cursor[i] = excl;
        g_dinv[i]   = rsqrtf((float)v + 1.0f);
    }
}

__global__ void fill_kernel(const int* __restrict__ src,
                            const int* __restrict__ dst, int E) {
    int i = blockIdx.x * blockDim.x + threadIdx.x;
    if (i < E) {
        int d = dst[i];
        int pos = atomicAdd(&g_cursor[d], 1);
        g_col[pos] = src[i];
    }
}

// ---------------- SGEMM fp32 out: C[M,N] = A[M,K] @ B[K,N] ----------------
__global__ __launch_bounds__(256)
void sgemm_kernel(const float* __restrict__ A, const float* __restrict__ B,
                  float* __restrict__ C, int M, int N, int K) {
    __shared__ float As[16][132];
    __shared__ float Bs[16][64];
    int t  = threadIdx.x;
    int bm = blockIdx.y * 128;
    int bn = blockIdx.x * 64;
    int ar0 = t >> 2;
    int akc = (t & 3) * 4;
    int br  = t >> 4;
    int bnc = (t & 15) * 4;
    int ty = t >> 4, tx = t & 15;

    float acc[8][4] = {};
    for (int k0 = 0; k0 < K; k0 += 16) {
#pragma unroll
        for (int h = 0; h < 2; h++) {
            int r = ar0 + h * 64;
            float4 av = make_float4(0.f, 0.f, 0.f, 0.f);
            if (bm + r < M) av = *(const float4*)&A[(size_t)(bm + r) * K + k0 + akc];
            As[akc + 0][r] = av.x;
            As[akc + 1][r] = av.y;
            As[akc + 2][r] = av.z;
            As[akc + 3][r] = av.w;
        }
        float4 bv = *(const float4*)&B[(size_t)(k0 + br) * N + bn + bnc];
        *(float4*)&Bs[br][bnc] = bv;
        __syncthreads();
#pragma unroll
        for (int k = 0; k < 16; k++) {
            float4 a0 = *(const float4*)&As[k][ty * 8];
            float4 a1 = *(const float4*)&As[k][ty * 8 + 4];
            float4 b  = *(const float4*)&Bs[k][tx * 4];
            float am[8] = {a0.x, a0.y, a0.z, a0.w, a1.x, a1.y, a1.z, a1.w};
#pragma unroll
            for (int i = 0; i < 8; i++) {
                acc[i][0] = fmaf(am[i], b.x, acc[i][0]);
                acc[i][1] = fmaf(am[i], b.y, acc[i][1]);
                acc[i][2] = fmaf(am[i], b.z, acc[i][2]);
                acc[i][3] = fmaf(am[i], b.w, acc[i][3]);
            }
        }
        __syncthreads();
    }
    int row0 = bm + ty * 8;
#pragma unroll
    for (int i = 0; i < 8; i++) {
        int row = row0 + i;
        if (row < M) {
            *(float4*)&C[(size_t)row * N + bn + tx * 4] =
                make_float4(acc[i][0], acc[i][1], acc[i][2], acc[i][3]);
        }
    }
}

// ---------------- SGEMM fp16 out: identical compute, half store -----------
__global__ __launch_bounds__(256)
void sgemm_f16_kernel(const float* __restrict__ A, const float* __restrict__ B,
                      __half* __restrict__ C, int M, int N, int K) {
    __shared__ float As[16][132];
    __shared__ float Bs[16][64];
    int t  = threadIdx.x;
    int bm = blockIdx.y * 128;
    int bn = blockIdx.x * 64;
    int ar0 = t >> 2;
    int akc = (t & 3) * 4;
    int br  = t >> 4;
    int bnc = (t & 15) * 4;
    int ty = t >> 4, tx = t & 15;

    float acc[8][4] = {};
    for (int k0 = 0; k0 < K; k0 += 16) {
#pragma unroll
        for (int h = 0; h < 2; h++) {
            int r = ar0 + h * 64;
            float4 av = make_float4(0.f, 0.f, 0.f, 0.f);
            if (bm + r < M) av = *(const float4*)&A[(size_t)(bm + r) * K + k0 + akc];
            As[akc + 0][r] = av.x;
            As[akc + 1][r] = av.y;
            As[akc + 2][r] = av.z;
            As[akc + 3][r] = av.w;
        }
        float4 bv = *(const float4*)&B[(size_t)(k0 + br) * N + bn + bnc];
        *(float4*)&Bs[br][bnc] = bv;
        __syncthreads();
#pragma unroll
        for (int k = 0; k < 16; k++) {
            float4 a0 = *(const float4*)&As[k][ty * 8];
            float4 a1 = *(const float4*)&As[k][ty * 8 + 4];
            float4 b  = *(const float4*)&Bs[k][tx * 4];
            float am[8] = {a0.x, a0.y, a0.z, a0.w, a1.x, a1.y, a1.z, a1.w};
#pragma unroll
            for (int i = 0; i < 8; i++) {
                acc[i][0] = fmaf(am[i], b.x, acc[i][0]);
                acc[i][1] = fmaf(am[i], b.y, acc[i][1]);
                acc[i][2] = fmaf(am[i], b.z, acc[i][2]);
                acc[i][3] = fmaf(am[i], b.w, acc[i][3]);
            }
        }
        __syncthreads();
    }
    int row0 = bm + ty * 8;
#pragma unroll
    for (int i = 0; i < 8; i++) {
        int row = row0 + i;
        if (row < M) {
            union { uint2 u; __half2 h[2]; } pk;
            pk.h[0] = __floats2half2_rn(acc[i][0], acc[i][1]);
            pk.h[1] = __floats2half2_rn(acc[i][2], acc[i][3]);
            *(uint2*)&C[(size_t)row * N + bn + tx * 4] = pk.u;
        }
    }
}

// ---------------- GCN aggregation: warp/node, fp16 gather, fp32 accum -----
template <bool RELU>
__global__ void agg128_kernel(const __half* __restrict__ xw,
                              float* __restrict__ out,
                              const float* __restrict__ bias) {
    int node = (blockIdx.x * blockDim.x + threadIdx.x) >> 5;
    int lane = threadIdx.x & 31;
    if (node >= NN) return;
    float di  = g_dinv[node];
    int   beg = g_rowptr[node], end = g_rowptr[node + 1];
    float4 acc = make_float4(0.f, 0.f, 0.f, 0.f);
    for (int base = beg; base < end; base += 32) {
        int m = end - base; if (m > 32) m = 32;
        int s = 0; float ds = 0.f;
        if (lane < m) { s = g_col[base + lane]; ds = g_dinv[s]; }
        int i = 0;
        for (; i + 8 <= m; i += 8) {
            int si[8]; float w[8]; uint2 xv[8];
#pragma unroll
            for (int j = 0; j < 8; j++) {
                si[j] = __shfl_sync(0xffffffffu, s,  i + j);
                w[j]  = __shfl_sync(0xffffffffu, ds, i + j);
            }
#pragma unroll
            for (int j = 0; j < 8; j++)
                xv[j] = *(const uint2*)(xw + (size_t)si[j] * 128 + lane * 4);
#pragma unroll
            for (int j = 0; j < 8; j++) {
                float2 lo = __half22float2(*(const __half2*)&xv[j].x);
                float2 hi = __half22float2(*(const __half2*)&xv[j].y);
                acc.x = fmaf(w[j], lo.x, acc.x);
                acc.y = fmaf(w[j], lo.y, acc.y);
                acc.z = fmaf(w[j], hi.x, acc.z);
                acc.w = fmaf(w[j], hi.y, acc.w);
            }
        }
        for (; i < m; i++) {
            int   si = __shfl_sync(0xffffffffu, s, i);
            float w  = __shfl_sync(0xffffffffu, ds, i);
            uint2 xv = *(const uint2*)(xw + (size_t)si * 128 + lane * 4);
            float2 lo = __half22float2(*(const __half2*)&xv.x);
            float2 hi = __half22float2(*(const __half2*)&xv.y);
            acc.x = fmaf(w, lo.x, acc.x); acc.y = fmaf(w, lo.y, acc.y);
            acc.z = fmaf(w, hi.x, acc.z); acc.w = fmaf(w, hi.y, acc.w);
        }
    }
    uint2 svp = *(const uint2*)(xw + (size_t)node * 128 + lane * 4);
    float2 slo = __half22float2(*(const __half2*)&svp.x);
    float2 shi = __half22float2(*(const __half2*)&svp.y);
    float4 b  = *(const float4*)(bias + lane * 4);
    float  d2 = di * di;
    float4 r;
    r.x = di * acc.x + d2 * slo.x + b.x;
    r.y = di * acc.y + d2 * slo.y + b.y;
    r.z = di * acc.z + d2 * shi.x + b.z;
    r.w = di * acc.w + d2 * shi.y + b.w;
    if (RELU) {
        r.x = fmaxf(r.x, 0.f); r.y = fmaxf(r.y, 0.f);
        r.z = fmaxf(r.z, 0.f); r.w = fmaxf(r.w, 0.f);
    }
    *(float4*)(out + (size_t)node * 128 + lane * 4) = r;
}

template <bool RELU>
__global__ void agg64_kernel(const __half* __restrict__ xw,
                             float* __restrict__ out,
                             const float* __restrict__ bias) {
    int node = (blockIdx.x * blockDim.x + threadIdx.x) >> 5;
    int lane = threadIdx.x & 31;
    if (node >= NN) return;
    float di  = g_dinv[node];
    int   beg = g_rowptr[node], end = g_rowptr[node + 1];
    float2 acc = make_float2(0.f, 0.f);
    for (int base = beg; base < end; base += 32) {
        int m = end - base; if (m > 32) m = 32;
        int s = 0; float ds = 0.f;
        if (lane < m) { s = g_col[base + lane]; ds = g_dinv[s]; }
        int i = 0;
        for (; i + 8 <= m; i += 8) {
            int si[8]; float w[8]; __half2 xv[8];
#pragma unroll
            for (int j = 0; j < 8; j++) {
                si[j] = __shfl_sync(0xffffffffu, s,  i + j);
                w[j]  = __shfl_sync(0xffffffffu, ds, i + j);
            }
#pragma unroll
            for (int j = 0; j < 8; j++)
                xv[j] = *(const __half2*)(xw + (size_t)si[j] * 64 + lane * 2);
#pragma unroll
            for (int j = 0; j < 8; j++) {
                float2 f = __half22float2(xv[j]);
                acc.x = fmaf(w[j], f.x, acc.x);
                acc.y = fmaf(w[j], f.y, acc.y);
            }
        }
        for (; i < m; i++) {
            int   si = __shfl_sync(0xffffffffu, s, i);
            float w  = __shfl_sync(0xffffffffu, ds, i);
            float2 f = __half22float2(*(const __half2*)(xw + (size_t)si * 64 + lane * 2));
            acc.x = fmaf(w, f.x, acc.x); acc.y = fmaf(w, f.y, acc.y);
        }
    }
    float2 sv = __half22float2(*(const __half2*)(xw + (size_t)node * 64 + lane * 2));
    float2 b  = *(const float2*)(bias + lane * 2);
    float  d2 = di * di;
    float2 r;
    r.x = di * acc.x + d2 * sv.x + b.x;
    r.y = di * acc.y + d2 * sv.y + b.y;
    if (RELU) { r.x = fmaxf(r.x, 0.f); r.y = fmaxf(r.y, 0.f); }
    *(float2*)(out + (size_t)node * 64 + lane * 2) = r;
}

// ---------------- pack W1 into [64,128] = [W1_top | W1_bot] ----------------
__global__ void build_wuv_kernel(const float* __restrict__ W1) {
    int k = blockIdx.x;    // 0..63
    int j = threadIdx.x;   // 0..127
    g_wuv[k * 128 + j] = (j < 64) ? W1[k * 64 + j] : W1[(64 + k) * 64 + (j - 64)];
}

// ---------------- decode: warp per label edge ----------------
__global__ void decode_kernel(const float* __restrict__ uv,
                              const int* __restrict__ eli,
                              const float* __restrict__ b1,
                              const float* __restrict__ W2,
                              const float* __restrict__ b2,
                              float* __restrict__ out, int EL) {
    int e    = (blockIdx.x * blockDim.x + threadIdx.x) >> 5;
    int lane = threadIdx.x & 31;
    if (e >= EL) return;
    int s = eli[e];
    int d = eli[EL + e];
    const float2* ps = (const float2*)(uv + (size_t)s * 128);
    const float2* pd = (const float2*)(uv + (size_t)d * 128);
    float2 u_s = ps[lane];
    float2 v_s = ps[32 + lane];
    float2 u_d = pd[lane];
    float2 v_d = pd[32 + lane];
    float2 bb = ((const float2*)b1)[lane];
    float2 ww = ((const float2*)W2)[lane];
    float sum = 0.f, h;
    h = u_s.x + v_d.x + bb.x; sum = fmaf(fmaxf(h, 0.f), ww.x, sum);
    h = u_s.y + v_d.y + bb.y; sum = fmaf(fmaxf(h, 0.f), ww.y, sum);
    h = u_d.x + v_s.x + bb.x; sum = fmaf(fmaxf(h, 0.f), ww.x, sum);
    h = u_d.y + v_s.y + bb.y; sum = fmaf(fmaxf(h, 0.f), ww.y, sum);
#pragma unroll
    for (int o = 16; o; o >>= 1) sum += __shfl_xor_sync(0xffffffffu, sum, o);
    if (lane == 0) {
        float val = 0.5f * sum + b2[0];
        out[e]      = -val;
        out[EL + e] =  val;
    }
}

// ---------------- launch ----------------
extern "C" void kernel_launch(void* const* d_in, const int* in_sizes, int n_in,
                              void* d_out, int out_size) {
    const float* x   = (const float*)d_in[0];
    const int*   ei  = (const int*)d_in[1];
    const int*   eli = (const int*)d_in[2];
    const float* Wc1 = (const float*)d_in[3];
    const float* bc1 = (const float*)d_in[4];
    const float* Wc2 = (const float*)d_in[5];
    const float* bc2 = (const float*)d_in[6];
    const float* W1  = (const float*)d_in[7];
    const float* b1  = (const float*)d_in[8];
    const float* W2  = (const float*)d_in[9];
    const float* b2  = (const float*)d_in[10];
    float* out = (float*)d_out;

    int E  = in_sizes[1] / 2;
    int EL = in_sizes[2] / 2;

    void *p_xw16, *p_h, *p_z, *p_uv, *p_deg, *p_wuv;
    cudaGetSymbolAddress(&p_xw16, g_xw16);
    cudaGetSymbolAddress(&p_h,    g_h);
    cudaGetSymbolAddress(&p_z,    g_z);
    cudaGetSymbolAddress(&p_uv,   g_uv);
    cudaGetSymbolAddress(&p_deg,  g_deg);
    cudaGetSymbolAddress(&p_wuv,  g_wuv);

    static cudaStream_t s1 = nullptr;
    static cudaEvent_t  evFork = nullptr, evJoin = nullptr;
    if (s1 == nullptr) {
        cudaStreamCreateWithFlags(&s1, cudaStreamNonBlocking);
        cudaEventCreateWithFlags(&evFork, cudaEventDisableTiming);
        cudaEventCreateWithFlags(&evJoin, cudaEventDisableTiming);
    }

    // ---- fork: CSR chain on s1, GEMM1 + wuv pack on main stream ----
    cudaEventRecord(evFork, 0);
    cudaStreamWaitEvent(s1, evFork, 0);

    cudaMemsetAsync(p_deg, 0, NN * sizeof(int), s1);
    hist_kernel<<<(E + 255) / 256, 256, 0, s1>>>(ei + E, E);
    scan_partial_kernel<<<NB, 256, 0, s1>>>();
    scan_offsets_kernel<<<1, 256, 0, s1>>>(E);
    scan_final_kernel<<<NB, 256, 0, s1>>>();
    fill_kernel<<<(E + 255) / 256, 256, 0, s1>>>(ei, ei + E, E);
    cudaEventRecord(evJoin, s1);

    // main stream (concurrent): xw16 = fp16(x @ Wc1) ; wuv pack
    sgemm_f16_kernel<<<dim3(2, (NN + 127) / 128), 256>>>(x, Wc1, (__half*)p_xw16, NN, 128, 128);
    build_wuv_kernel<<<64, 128>>>(W1);

    // ---- join: aggregation needs CSR + dinv + xw16 ----
    cudaStreamWaitEvent(0, evJoin, 0);

    agg128_kernel<true><<<(NN + 7) / 8, 256>>>((const __half*)p_xw16, (float*)p_h, bc1);

    // ---- layer 2: hw16 = fp16(h @ Wc2) (reuse g_xw16) ; z = agg ----
    sgemm_f16_kernel<<<dim3(1, (NN + 127) / 128), 256>>>((const float*)p_h, Wc2, (__half*)p_xw16, NN, 64, 128);
    agg64_kernel<false><<<(NN + 7) / 8, 256>>>((const __half*)p_xw16, (float*)p_z, bc2);

    // ---- decode precompute: uv = z @ [W1_top | W1_bot] ----
    sgemm_kernel<<<dim3(2, (NN + 127) / 128), 256>>>((const float*)p_z, (const float*)p_wuv,
                                                     (float*)p_uv, NN, 128, 64);

    // ---- decode per label edge ----
    decode_kernel<<<(EL * 32 + 255) / 256, 256>>>((const float*)p_uv, eli, b1, W2, b2, out, EL);
}

// round 10
// speedup vs baseline: 1.4396x; 1.0326x over previous
#include <cuda_runtime.h>
#include <cuda_fp16.h>
#include <cstdint>
#include <math.h>

#define NN  50000
#define EE  1600000
#define NB  ((NN + 255) / 256)

// ---------------- scratch (device globals; no allocation) ----------------
__device__ __half g_xs [NN * 256];   // x split  [hi(128) | lo(128)]
__device__ __half g_hs [NN * 256];   // h split  [hi | lo]
__device__ __half g_zs [NN * 128];   // z split  [hi(64) | lo(64)]
__device__ __half g_xw16[NN * 128];  // fp16 gathered features (xw, then hw)
__device__ float  g_uv[NN * 128];    // [u | v] per node (fp32, decode input)
__device__ float  g_dinv[NN];
__device__ int    g_deg[NN];
__device__ int    g_rowptr[NN + 1];
__device__ int    g_cursor[NN];
__device__ int    g_col[EE];
__device__ int    g_partial[256];
__device__ __half g_wc1c[384 * 128]; // [Wc1hi; Wc1hi; Wc1lo]
__device__ __half g_wc2c[384 * 64];
__device__ __half g_wuvc[192 * 128]; // packed [W1top|W1bot] split-cat

// ---------------- CSR build ----------------
__global__ void hist_kernel(const int* __restrict__ dst, int E) {
    int i = blockIdx.x * blockDim.x + threadIdx.x;
    if (i < E) atomicAdd(&g_deg[dst[i]], 1);
}

__global__ void scan_partial_kernel() {
    __shared__ int ws[8];
    int i = blockIdx.x * 256 + threadIdx.x;
    int t = threadIdx.x;
    int v = (i < NN) ? g_deg[i] : 0;
#pragma unroll
    for (int o = 16; o; o >>= 1) v += __shfl_xor_sync(0xffffffffu, v, o);
    if ((t & 31) == 0) ws[t >> 5] = v;
    __syncthreads();
    if (t < 8) {
        int s = ws[t];
#pragma unroll
        for (int o = 4; o; o >>= 1) s += __shfl_xor_sync(0xffu, s, o);
        if (t == 0) g_partial[blockIdx.x] = s;
    }
}

__global__ void scan_offsets_kernel(int E) {
    __shared__ int sm[256];
    int t = threadIdx.x;
    int v = (t < NB) ? g_partial[t] : 0;
    sm[t] = v;
    __syncthreads();
#pragma unroll
    for (int off = 1; off < 256; off <<= 1) {
        int a = (t >= off) ? sm[t - off] : 0;
        __syncthreads();
        sm[t] += a;
        __syncthreads();
    }
    if (t < NB) g_partial[t] = sm[t] - v;
    if (t == 0) g_rowptr[NN] = E;
}

__global__ void scan_final_kernel() {
    __shared__ int sm[256];
    int i = blockIdx.x * 256 + threadIdx.x;
    int t = threadIdx.x;
    int v = (i < NN) ? g_deg[i] : 0;
    sm[t] = v;
    __syncthreads();
#pragma unroll
    for (int off = 1; off < 256; off <<= 1) {
        int a = (t >= off) ? sm[t - off] : 0;
        __syncthreads();
        sm[t] += a;
        __syncthreads();
    }
    if (i < NN) {
        int excl = g_partial[blockIdx.x] + sm[t] - v;
        g_rowptr[i] = excl;
        g_cursor[i] = excl;
        g_dinv[i]   = rsqrtf((float)v + 1.0f);
    }
}

__global__ void fill_kernel(const int* __restrict__ src,
                            const int* __restrict__ dst, int E) {
    int i = blockIdx.x * blockDim.x + threadIdx.x;
    if (i < E) {
        int d = dst[i];
        int pos = atomicAdd(&g_cursor[d], 1);
        g_col[pos] = src[i];
    }
}

// ---------------- split/cat prep ----------------
// x [NN,128] fp32 -> g_xs [NN, hi(128)|lo(128)] fp16
__global__ void split_x_kernel(const float* __restrict__ x) {
    int i = blockIdx.x * blockDim.x + threadIdx.x;   // one per 4 floats
    if (i >= NN * 32) return;
    float4 v = ((const float4*)x)[i];
    int node = i >> 5, q = (i & 31) * 4;
    __half2 h01 = __floats2half2_rn(v.x, v.y);
    __half2 h23 = __floats2half2_rn(v.z, v.w);
    float2 f01 = __half22float2(h01);
    float2 f23 = __half22float2(h23);
    __half2 l01 = __floats2half2_rn(v.x - f01.x, v.y - f01.y);
    __half2 l23 = __floats2half2_rn(v.z - f23.x, v.w - f23.y);
    __half2* hp = (__half2*)(g_xs + (size_t)node * 256 + q);
    hp[0] = h01; hp[1] = h23;
    __half2* lp = (__half2*)(g_xs + (size_t)node * 256 + 128 + q);
    lp[0] = l01; lp[1] = l23;
}

// W [K,N] fp32 -> out [3K,N] fp16 = [hi; hi; lo]
__global__ void build_cat_kernel(const float* __restrict__ W, __half* __restrict__ out,
                                 int K, int N) {
    int r = blockIdx.x, n = threadIdx.x;
    int k = (r < K) ? r : ((r < 2 * K) ? r - K : r - 2 * K);
    float w = W[(size_t)k * N + n];
    __half h = __float2half_rn(w);
    out[(size_t)r * N + n] = (r < 2 * K) ? h : __float2half_rn(w - __half2float(h));
}

// W1 [128,64] -> packed W'[64,128]=[W1top|W1bot] -> cat [192,128]
__global__ void build_wuvcat_kernel(const float* __restrict__ W1) {
    int r = blockIdx.x, j = threadIdx.x;             // r<192, j<128
    int k = (r < 64) ? r : ((r < 128) ? r - 64 : r - 128);
    float w = (j < 64) ? W1[k * 64 + j] : W1[(64 + k) * 64 + (j - 64)];
    __half h = __float2half_rn(w);
    g_wuvc[(size_t)r * 128 + j] = (r < 128) ? h : __float2half_rn(w - __half2float(h));
}

// ---------------- TC GEMM: C[M,N] = (Ahi+Alo) @ W via K'=3K fp16 mma ------
// A: [M, 2K] halves = [hi|lo]; B: [3K, N] halves; block 128x64, 8 warps.
__device__ __forceinline__ void ldm4(unsigned int* a, unsigned int addr) {
    asm volatile("ldmatrix.sync.aligned.m8n8.x4.shared.b16 {%0,%1,%2,%3}, [%4];"
                 : "=r"(a[0]), "=r"(a[1]), "=r"(a[2]), "=r"(a[3]) : "r"(addr));
}
__device__ __forceinline__ void ldm4t(unsigned int* b, unsigned int addr) {
    asm volatile("ldmatrix.sync.aligned.m8n8.x4.trans.shared.b16 {%0,%1,%2,%3}, [%4];"
                 : "=r"(b[0]), "=r"(b[1]), "=r"(b[2]), "=r"(b[3]) : "r"(addr));
}
__device__ __forceinline__ void mma16816(float* d, const unsigned int* a, const unsigned int* b) {
    asm volatile("mma.sync.aligned.m16n8k16.row.col.f32.f16.f16.f32 "
                 "{%0,%1,%2,%3}, {%4,%5,%6,%7}, {%8,%9}, {%0,%1,%2,%3};"
                 : "+f"(d[0]), "+f"(d[1]), "+f"(d[2]), "+f"(d[3])
                 : "r"(a[0]), "r"(a[1]), "r"(a[2]), "r"(a[3]), "r"(b[0]), "r"(b[1]));
}

template <bool HALF_OUT>
__global__ __launch_bounds__(256)
void tcgemm_kernel(const __half* __restrict__ A, const __half* __restrict__ B,
                   void* __restrict__ Cv, int M, int N, int K) {
    __shared__ __half As[128 * 72];
    __shared__ __half Bs[64 * 72];
    int t = threadIdx.x;
    int bm = blockIdx.y * 128;
    int bn = blockIdx.x * 64;
    int warp = t >> 5, lane = t & 31;
    int wr = warp & 3, wc = warp >> 2;
    int strideA = 2 * K;
    int nChunks = (3 * K) / 64;

    unsigned int asb = (unsigned int)__cvta_generic_to_shared(As);
    unsigned int bsb = (unsigned int)__cvta_generic_to_shared(Bs);

    float acc[2][4][4];
#pragma unroll
    for (int i = 0; i < 2; i++)
#pragma unroll
        for (int j = 0; j < 4; j++)
#pragma unroll
            for (int q = 0; q < 4; q++) acc[i][j][q] = 0.f;

    int ar = t >> 1, aq = t & 1;       // A: 2 threads/row, 32 halves each
    int brr = t >> 2, bp = t & 3;      // B: 4 threads/row, 16 halves each

    for (int c = 0; c < nChunks; c++) {
        int L = c * 64;
        int srcA = (L < 2 * K) ? L : L - 2 * K;
        __syncthreads();
        // A chunk: rows bm..bm+127, cols srcA..+63
        {
            uint4 z = make_uint4(0, 0, 0, 0);
            const uint4* src = (const uint4*)(A + (size_t)(bm + ar) * strideA + srcA + aq * 32);
            uint4* dst = (uint4*)(As + ar * 72 + aq * 32);
            bool ok = (bm + ar) < M;
#pragma unroll
            for (int i = 0; i < 4; i++) dst[i] = ok ? src[i] : z;
        }
        // B chunk: rows L..L+63, cols bn..bn+63
        {
            const uint4* src = (const uint4*)(B + (size_t)(L + brr) * N + bn + bp * 16);
            uint4* dst = (uint4*)(Bs + brr * 72 + bp * 16);
            dst[0] = src[0];
            dst[1] = src[1];
        }
        __syncthreads();
#pragma unroll
        for (int kk = 0; kk < 4; kk++) {
            unsigned int a[2][4], b[2][4];
#pragma unroll
            for (int i = 0; i < 2; i++) {
                int row = wr * 32 + i * 16 + (lane & 15);
                ldm4(a[i], asb + (unsigned int)(row * 72 + kk * 16 + (lane >> 4) * 8) * 2u);
            }
#pragma unroll
            for (int g = 0; g < 2; g++) {
                int krow = kk * 16 + (lane & 15);
                ldm4t(b[g], bsb + (unsigned int)(krow * 72 + wc * 32 + g * 16 + (lane >> 4) * 8) * 2u);
            }
#pragma unroll
            for (int i = 0; i < 2; i++)
#pragma unroll
                for (int j = 0; j < 4; j++)
                    mma16816(acc[i][j], a[i], &b[j >> 1][(j & 1) * 2]);
        }
    }

    int lrow = lane >> 2, lcol = (lane & 3) * 2;
#pragma unroll
    for (int i = 0; i < 2; i++) {
#pragma unroll
        for (int j = 0; j < 4; j++) {
            int row = bm + wr * 32 + i * 16 + lrow;
            int col = bn + wc * 32 + j * 8 + lcol;
            if (HALF_OUT) {
                __half* C = (__half*)Cv;
                if (row < M)
                    *(__half2*)&C[(size_t)row * N + col] =
                        __floats2half2_rn(acc[i][j][0], acc[i][j][1]);
                if (row + 8 < M)
                    *(__half2*)&C[(size_t)(row + 8) * N + col] =
                        __floats2half2_rn(acc[i][j][2], acc[i][j][3]);
            } else {
                float* C = (float*)Cv;
                if (row < M)
                    *(float2*)&C[(size_t)row * N + col] =
                        make_float2(acc[i][j][0], acc[i][j][1]);
                if (row + 8 < M)
                    *(float2*)&C[(size_t)(row + 8) * N + col] =
                        make_float2(acc[i][j][2], acc[i][j][3]);
            }
        }
    }
}

// ---------------- GCN aggregation (fp16 gather, fp32 accum, split out) ----
__global__ void agg128_kernel(const __half* __restrict__ xw,
                              const float* __restrict__ bias) {
    int node = (blockIdx.x * blockDim.x + threadIdx.x) >> 5;
    int lane = threadIdx.x & 31;
    if (node >= NN) return;
    float di  = g_dinv[node];
    int   beg = g_rowptr[node], end = g_rowptr[node + 1];
    float4 acc = make_float4(0.f, 0.f, 0.f, 0.f);
    for (int base = beg; base < end; base += 32) {
        int m = end - base; if (m > 32) m = 32;
        int s = 0; float ds = 0.f;
        if (lane < m) { s = g_col[base + lane]; ds = g_dinv[s]; }
        int i = 0;
        for (; i + 8 <= m; i += 8) {
            int si[8]; float w[8]; uint2 xv[8];
#pragma unroll
            for (int j = 0; j < 8; j++) {
                si[j] = __shfl_sync(0xffffffffu, s,  i + j);
                w[j]  = __shfl_sync(0xffffffffu, ds, i + j);
            }
#pragma unroll
            for (int j = 0; j < 8; j++)
                xv[j] = *(const uint2*)(xw + (size_t)si[j] * 128 + lane * 4);
#pragma unroll
            for (int j = 0; j < 8; j++) {
                float2 lo = __half22float2(*(const __half2*)&xv[j].x);
                float2 hi = __half22float2(*(const __half2*)&xv[j].y);
                acc.x = fmaf(w[j], lo.x, acc.x);
                acc.y = fmaf(w[j], lo.y, acc.y);
                acc.z = fmaf(w[j], hi.x, acc.z);
                acc.w = fmaf(w[j], hi.y, acc.w);
            }
        }
        for (; i < m; i++) {
            int   si = __shfl_sync(0xffffffffu, s, i);
            float w  = __shfl_sync(0xffffffffu, ds, i);
            uint2 xv = *(const uint2*)(xw + (size_t)si * 128 + lane * 4);
            float2 lo = __half22float2(*(const __half2*)&xv.x);
            float2 hi = __half22float2(*(const __half2*)&xv.y);
            acc.x = fmaf(w, lo.x, acc.x); acc.y = fmaf(w, lo.y, acc.y);
            acc.z = fmaf(w, hi.x, acc.z); acc.w = fmaf(w, hi.y, acc.w);
        }
    }
    uint2 svp = *(const uint2*)(xw + (size_t)node * 128 + lane * 4);
    float2 slo = __half22float2(*(const __half2*)&svp.x);
    float2 shi = __half22float2(*(const __half2*)&svp.y);
    float4 b  = *(const float4*)(bias + lane * 4);
    float  d2 = di * di;
    float4 r;
    r.x = fmaxf(di * acc.x + d2 * slo.x + b.x, 0.f);
    r.y = fmaxf(di * acc.y + d2 * slo.y + b.y, 0.f);
    r.z = fmaxf(di * acc.z + d2 * shi.x + b.z, 0.f);
    r.w = fmaxf(di * acc.w + d2 * shi.y + b.w, 0.f);
    // split-fp16 output: hi | lo
    __half2 h01 = __floats2half2_rn(r.x, r.y);
    __half2 h23 = __floats2half2_rn(r.z, r.w);
    float2 f01 = __half22float2(h01), f23 = __half22float2(h23);
    __half2 l01 = __floats2half2_rn(r.x - f01.x, r.y - f01.y);
    __half2 l23 = __floats2half2_rn(r.z - f23.x, r.w - f23.y);
    __half2* hp = (__half2*)(g_hs + (size_t)node * 256 + lane * 4);
    hp[0] = h01; hp[1] = h23;
    __half2* lp = (__half2*)(g_hs + (size_t)node * 256 + 128 + lane * 4);
    lp[0] = l01; lp[1] = l23;
}

__global__ void agg64_kernel(const __half* __restrict__ xw,
                             const float* __restrict__ bias) {
    int node = (blockIdx.x * blockDim.x + threadIdx.x) >> 5;
    int lane = threadIdx.x & 31;
    if (node >= NN) return;
    float di  = g_dinv[node];
    int   beg = g_rowptr[node], end = g_rowptr[node + 1];
    float2 acc = make_float2(0.f, 0.f);
    for (int base = beg; base < end; base += 32) {
        int m = end - base; if (m > 32) m = 32;
        int s = 0; float ds = 0.f;
        if (lane < m) { s = g_col[base + lane]; ds = g_dinv[s]; }
        int i = 0;
        for (; i + 8 <= m; i += 8) {
            int si[8]; float w[8]; __half2 xv[8];
#pragma unroll
            for (int j = 0; j < 8; j++) {
                si[j] = __shfl_sync(0xffffffffu, s,  i + j);
                w[j]  = __shfl_sync(0xffffffffu, ds, i + j);
            }
#pragma unroll
            for (int j = 0; j < 8; j++)
                xv[j] = *(const __half2*)(xw + (size_t)si[j] * 64 + lane * 2);
#pragma unroll
            for (int j = 0; j < 8; j++) {
                float2 f = __half22float2(xv[j]);
                acc.x = fmaf(w[j], f.x, acc.x);
                acc.y = fmaf(w[j], f.y, acc.y);
            }
        }
        for (; i < m; i++) {
            int   si = __shfl_sync(0xffffffffu, s, i);
            float w  = __shfl_sync(0xffffffffu, ds, i);
            float2 f = __half22float2(*(const __half2*)(xw + (size_t)si * 64 + lane * 2));
            acc.x = fmaf(w, f.x, acc.x); acc.y = fmaf(w, f.y, acc.y);
        }
    }
    float2 sv = __half22float2(*(const __half2*)(xw + (size_t)node * 64 + lane * 2));
    float2 b  = *(const float2*)(bias + lane * 2);
    float  d2 = di * di;
    float rx = di * acc.x + d2 * sv.x + b.x;
    float ry = di * acc.y + d2 * sv.y + b.y;
    __half2 h = __floats2half2_rn(rx, ry);
    float2 f = __half22float2(h);
    __half2 l = __floats2half2_rn(rx - f.x, ry - f.y);
    *(__half2*)(g_zs + (size_t)node * 128 + lane * 2) = h;
    *(__half2*)(g_zs + (size_t)node * 128 + 64 + lane * 2) = l;
}

// ---------------- decode: warp per label edge ----------------
__global__ void decode_kernel(const float* __restrict__ uv,
                              const int* __restrict__ eli,
                              const float* __restrict__ b1,
                              const float* __restrict__ W2,
                              const float* __restrict__ b2,
                              float* __restrict__ out, int EL) {
    int e    = (blockIdx.x * blockDim.x + threadIdx.x) >> 5;
    int lane = threadIdx.x & 31;
    if (e >= EL) return;
    int s = eli[e];
    int d = eli[EL + e];
    const float2* ps = (const float2*)(uv + (size_t)s * 128);
    const float2* pd = (const float2*)(uv + (size_t)d * 128);
    float2 u_s = ps[lane];
    float2 v_s = ps[32 + lane];
    float2 u_d = pd[lane];
    float2 v_d = pd[32 + lane];
    float2 bb = ((const float2*)b1)[lane];
    float2 ww = ((const float2*)W2)[lane];
    float sum = 0.f, h;
    h = u_s.x + v_d.x + bb.x; sum = fmaf(fmaxf(h, 0.f), ww.x, sum);
    h = u_s.y + v_d.y + bb.y; sum = fmaf(fmaxf(h, 0.f), ww.y, sum);
    h = u_d.x + v_s.x + bb.x; sum = fmaf(fmaxf(h, 0.f), ww.x, sum);
    h = u_d.y + v_s.y + bb.y; sum = fmaf(fmaxf(h, 0.f), ww.y, sum);
#pragma unroll
    for (int o = 16; o; o >>= 1) sum += __shfl_xor_sync(0xffffffffu, sum, o);
    if (lane == 0) {
        float val = 0.5f * sum + b2[0];
        out[e]      = -val;
        out[EL + e] =  val;
    }
}

// ---------------- launch ----------------
extern "C" void kernel_launch(void* const* d_in, const int* in_sizes, int n_in,
                              void* d_out, int out_size) {
    const float* x   = (const float*)d_in[0];
    const int*   ei  = (const int*)d_in[1];
    const int*   eli = (const int*)d_in[2];
    const float* Wc1 = (const float*)d_in[3];
    const float* bc1 = (const float*)d_in[4];
    const float* Wc2 = (const float*)d_in[5];
    const float* bc2 = (const float*)d_in[6];
    const float* W1  = (const float*)d_in[7];
    const float* b1  = (const float*)d_in[8];
    const float* W2  = (const float*)d_in[9];
    const float* b2  = (const float*)d_in[10];
    float* out = (float*)d_out;

    int E  = in_sizes[1] / 2;
    int EL = in_sizes[2] / 2;

    void *p_xs, *p_hs, *p_zs, *p_xw16, *p_uv, *p_deg, *p_wc1c, *p_wc2c, *p_wuvc;
    cudaGetSymbolAddress(&p_xs,   g_xs);
    cudaGetSymbolAddress(&p_hs,   g_hs);
    cudaGetSymbolAddress(&p_zs,   g_zs);
    cudaGetSymbolAddress(&p_xw16, g_xw16);
    cudaGetSymbolAddress(&p_uv,   g_uv);
    cudaGetSymbolAddress(&p_deg,  g_deg);
    cudaGetSymbolAddress(&p_wc1c, g_wc1c);
    cudaGetSymbolAddress(&p_wc2c, g_wc2c);
    cudaGetSymbolAddress(&p_wuvc, g_wuvc);

    static cudaStream_t s1 = nullptr;
    static cudaEvent_t  evFork = nullptr, evJoin = nullptr;
    if (s1 == nullptr) {
        cudaStreamCreateWithFlags(&s1, cudaStreamNonBlocking);
        cudaEventCreateWithFlags(&evFork, cudaEventDisableTiming);
        cudaEventCreateWithFlags(&evJoin, cudaEventDisableTiming);
    }

    int gy = (NN + 127) / 128;   // 391

    // ---- fork: CSR chain on s1 ----
    cudaEventRecord(evFork, 0);
    cudaStreamWaitEvent(s1, evFork, 0);
    cudaMemsetAsync(p_deg, 0, NN * sizeof(int), s1);
    hist_kernel<<<(E + 255) / 256, 256, 0, s1>>>(ei + E, E);
    scan_partial_kernel<<<NB, 256, 0, s1>>>();
    scan_offsets_kernel<<<1, 256, 0, s1>>>(E);
    scan_final_kernel<<<NB, 256, 0, s1>>>();
    fill_kernel<<<(E + 255) / 256, 256, 0, s1>>>(ei, ei + E, E);
    cudaEventRecord(evJoin, s1);

    // main stream (concurrent): prep + GEMM1
    split_x_kernel<<<(NN * 32 + 255) / 256, 256>>>(x);
    build_cat_kernel<<<384, 128>>>(Wc1, (__half*)p_wc1c, 128, 128);
    build_cat_kernel<<<384, 64>>>(Wc2, (__half*)p_wc2c, 128, 64);
    build_wuvcat_kernel<<<192, 128>>>(W1);
    tcgemm_kernel<true><<<dim3(2, gy), 256>>>((const __half*)p_xs, (const __half*)p_wc1c,
                                              p_xw16, NN, 128, 128);

    // ---- join ----
    cudaStreamWaitEvent(0, evJoin, 0);

    agg128_kernel<<<(NN + 7) / 8, 256>>>((const __half*)p_xw16, bc1);
    tcgemm_kernel<true><<<dim3(1, gy), 256>>>((const __half*)p_hs, (const __half*)p_wc2c,
                                              p_xw16, NN, 64, 128);
    agg64_kernel<<<(NN + 7) / 8, 256>>>((const __half*)p_xw16, bc2);
    tcgemm_kernel<false><<<dim3(2, gy), 256>>>((const __half*)p_zs, (const __half*)p_wuvc,
                                               p_uv, NN, 128, 64);
    decode_kernel<<<(EL * 32 + 255) / 256, 256>>>((const float*)p_uv, eli, b1, W2, b2, out, EL);
}

// round 11
// speedup vs baseline: 1.4457x; 1.0042x over previous
#include <cuda_runtime.h>
#include <cuda_fp16.h>
#include <cstdint>
#include <math.h>

#define NN  50000
#define EE  1600000
#define NB  ((NN + 255) / 256)

// ---------------- scratch (device globals; no allocation) ----------------
__device__ __half g_xs [NN * 256];   // x split  [hi(128) | lo(128)]
__device__ __half g_hs [NN * 256];   // h split  [hi | lo]
__device__ __half g_zs [NN * 128];   // z split  [hi(64) | lo(64)]
__device__ __half g_xw16[NN * 128];  // fp16 gathered features (xw, hw, then uv)
__device__ float  g_dinv[NN];
__device__ int    g_deg[NN];
__device__ int    g_rowptr[NN + 1];
__device__ int    g_cursor[NN];
__device__ int    g_col[EE];
__device__ int    g_partial[256];
__device__ __half g_wc1c[384 * 128]; // [Wc1hi; Wc1hi; Wc1lo]
__device__ __half g_wc2c[384 * 64];
__device__ __half g_wuvc[192 * 128]; // packed [W1top|W1bot] split-cat

// ---------------- CSR build ----------------
// 4 edges per thread: int4 load, 4 independent atomics in flight (MLP=4)
__global__ void hist_kernel(const int* __restrict__ dst, int E) {
    int i = blockIdx.x * blockDim.x + threadIdx.x;
    int E4 = E >> 2;
    if (i < E4) {
        int4 d = ((const int4*)dst)[i];
        atomicAdd(&g_deg[d.x], 1);
        atomicAdd(&g_deg[d.y], 1);
        atomicAdd(&g_deg[d.z], 1);
        atomicAdd(&g_deg[d.w], 1);
    }
    if (i == 0) {
        for (int r = E & ~3; r < E; r++) atomicAdd(&g_deg[dst[r]], 1);
    }
}

__global__ void scan_partial_kernel() {
    __shared__ int ws[8];
    int i = blockIdx.x * 256 + threadIdx.x;
    int t = threadIdx.x;
    int v = (i < NN) ? g_deg[i] : 0;
#pragma unroll
    for (int o = 16; o; o >>= 1) v += __shfl_xor_sync(0xffffffffu, v, o);
    if ((t & 31) == 0) ws[t >> 5] = v;
    __syncthreads();
    if (t < 8) {
        int s = ws[t];
#pragma unroll
        for (int o = 4; o; o >>= 1) s += __shfl_xor_sync(0xffu, s, o);
        if (t == 0) g_partial[blockIdx.x] = s;
    }
}

__global__ void scan_offsets_kernel(int E) {
    __shared__ int sm[256];
    int t = threadIdx.x;
    int v = (t < NB) ? g_partial[t] : 0;
    sm[t] = v;
    __syncthreads();
#pragma unroll
    for (int off = 1; off < 256; off <<= 1) {
        int a = (t >= off) ? sm[t - off] : 0;
        __syncthreads();
        sm[t] += a;
        __syncthreads();
    }
    if (t < NB) g_partial[t] = sm[t] - v;
    if (t == 0) g_rowptr[NN] = E;
}

__global__ void scan_final_kernel() {
    __shared__ int sm[256];
    int i = blockIdx.x * 256 + threadIdx.x;
    int t = threadIdx.x;
    int v = (i < NN) ? g_deg[i] : 0;
    sm[t] = v;
    __syncthreads();
#pragma unroll
    for (int off = 1; off < 256; off <<= 1) {
        int a = (t >= off) ? sm[t - off] : 0;
        __syncthreads();
        sm[t] += a;
        __syncthreads();
    }
    if (i < NN) {
        int excl = g_partial[blockIdx.x] + sm[t] - v;
        g_rowptr[i] = excl;
        g_cursor[i] = excl;
        g_dinv[i]   = rsqrtf((float)v + 1.0f);
    }
}

// 4 edges per thread, 4 atomic cursors in flight
__global__ void fill_kernel(const int* __restrict__ src,
                            const int* __restrict__ dst, int E) {
    int i = blockIdx.x * blockDim.x + threadIdx.x;
    int E4 = E >> 2;
    if (i < E4) {
        int4 s4 = ((const int4*)src)[i];
        int4 d4 = ((const int4*)dst)[i];
        int p0 = atomicAdd(&g_cursor[d4.x], 1);
        int p1 = atomicAdd(&g_cursor[d4.y], 1);
        int p2 = atomicAdd(&g_cursor[d4.z], 1);
        int p3 = atomicAdd(&g_cursor[d4.w], 1);
        g_col[p0] = s4.x;
        g_col[p1] = s4.y;
        g_col[p2] = s4.z;
        g_col[p3] = s4.w;
    }
    if (i == 0) {
        for (int r = E & ~3; r < E; r++) {
            int pos = atomicAdd(&g_cursor[dst[r]], 1);
            g_col[pos] = src[r];
        }
    }
}

// ---------------- split/cat prep ----------------
__global__ void split_x_kernel(const float* __restrict__ x) {
    int i = blockIdx.x * blockDim.x + threadIdx.x;   // one per 4 floats
    if (i >= NN * 32) return;
    float4 v = ((const float4*)x)[i];
    int node = i >> 5, q = (i & 31) * 4;
    __half2 h01 = __floats2half2_rn(v.x, v.y);
    __half2 h23 = __floats2half2_rn(v.z, v.w);
    float2 f01 = __half22float2(h01);
    float2 f23 = __half22float2(h23);
    __half2 l01 = __floats2half2_rn(v.x - f01.x, v.y - f01.y);
    __half2 l23 = __floats2half2_rn(v.z - f23.x, v.w - f23.y);
    __half2* hp = (__half2*)(g_xs + (size_t)node * 256 + q);
    hp[0] = h01; hp[1] = h23;
    __half2* lp = (__half2*)(g_xs + (size_t)node * 256 + 128 + q);
    lp[0] = l01; lp[1] = l23;
}

__global__ void build_cat_kernel(const float* __restrict__ W, __half* __restrict__ out,
                                 int K, int N) {
    int r = blockIdx.x, n = threadIdx.x;
    int k = (r < K) ? r : ((r < 2 * K) ? r - K : r - 2 * K);
    float w = W[(size_t)k * N + n];
    __half h = __float2half_rn(w);
    out[(size_t)r * N + n] = (r < 2 * K) ? h : __float2half_rn(w - __half2float(h));
}

__global__ void build_wuvcat_kernel(const float* __restrict__ W1) {
    int r = blockIdx.x, j = threadIdx.x;             // r<192, j<128
    int k = (r < 64) ? r : ((r < 128) ? r - 64 : r - 128);
    float w = (j < 64) ? W1[k * 64 + j] : W1[(64 + k) * 64 + (j - 64)];
    __half h = __float2half_rn(w);
    g_wuvc[(size_t)r * 128 + j] = (r < 128) ? h : __float2half_rn(w - __half2float(h));
}

// ---------------- TC GEMM: C[M,N] = (Ahi+Alo) @ W via K'=3K fp16 mma ------
__device__ __forceinline__ void ldm4(unsigned int* a, unsigned int addr) {
    asm volatile("ldmatrix.sync.aligned.m8n8.x4.shared.b16 {%0,%1,%2,%3}, [%4];"
                 : "=r"(a[0]), "=r"(a[1]), "=r"(a[2]), "=r"(a[3]) : "r"(addr));
}
__device__ __forceinline__ void ldm4t(unsigned int* b, unsigned int addr) {
    asm volatile("ldmatrix.sync.aligned.m8n8.x4.trans.shared.b16 {%0,%1,%2,%3}, [%4];"
                 : "=r"(b[0]), "=r"(b[1]), "=r"(b[2]), "=r"(b[3]) : "r"(addr));
}
__device__ __forceinline__ void mma16816(float* d, const unsigned int* a, const unsigned int* b) {
    asm volatile("mma.sync.aligned.m16n8k16.row.col.f32.f16.f16.f32 "
                 "{%0,%1,%2,%3}, {%4,%5,%6,%7}, {%8,%9}, {%0,%1,%2,%3};"
                 : "+f"(d[0]), "+f"(d[1]), "+f"(d[2]), "+f"(d[3])
                 : "r"(a[0]), "r"(a[1]), "r"(a[2]), "r"(a[3]), "r"(b[0]), "r"(b[1]));
}

template <bool HALF_OUT>
__global__ __launch_bounds__(256)
void tcgemm_kernel(const __half* __restrict__ A, const __half* __restrict__ B,
                   void* __restrict__ Cv, int M, int N, int K) {
    __shared__ __half As[128 * 72];
    __shared__ __half Bs[64 * 72];
    int t = threadIdx.x;
    int bm = blockIdx.y * 128;
    int bn = blockIdx.x * 64;
    int warp = t >> 5, lane = t & 31;
    int wr = warp & 3, wc = warp >> 2;
    int strideA = 2 * K;
    int nChunks = (3 * K) / 64;

    unsigned int asb = (unsigned int)__cvta_generic_to_shared(As);
    unsigned int bsb = (unsigned int)__cvta_generic_to_shared(Bs);

    float acc[2][4][4];
#pragma unroll
    for (int i = 0; i < 2; i++)
#pragma unroll
        for (int j = 0; j < 4; j++)
#pragma unroll
            for (int q = 0; q < 4; q++) acc[i][j][q] = 0.f;

    int ar = t >> 1, aq = t & 1;
    int brr = t >> 2, bp = t & 3;

    for (int c = 0; c < nChunks; c++) {
        int L = c * 64;
        int srcA = (L < 2 * K) ? L : L - 2 * K;
        __syncthreads();
        {
            uint4 z = make_uint4(0, 0, 0, 0);
            const uint4* src = (const uint4*)(A + (size_t)(bm + ar) * strideA + srcA + aq * 32);
            uint4* dst = (uint4*)(As + ar * 72 + aq * 32);
            bool ok = (bm + ar) < M;
#pragma unroll
            for (int i = 0; i < 4; i++) dst[i] = ok ? src[i] : z;
        }
        {
            const uint4* src = (const uint4*)(B + (size_t)(L + brr) * N + bn + bp * 16);
            uint4* dst = (uint4*)(Bs + brr * 72 + bp * 16);
            dst[0] = src[0];
            dst[1] = src[1];
        }
        __syncthreads();
#pragma unroll
        for (int kk = 0; kk < 4; kk++) {
            unsigned int a[2][4], b[2][4];
#pragma unroll
            for (int i = 0; i < 2; i++) {
                int row = wr * 32 + i * 16 + (lane & 15);
                ldm4(a[i], asb + (unsigned int)(row * 72 + kk * 16 + (lane >> 4) * 8) * 2u);
            }
#pragma unroll
            for (int g = 0; g < 2; g++) {
                int krow = kk * 16 + (lane & 15);
                ldm4t(b[g], bsb + (unsigned int)(krow * 72 + wc * 32 + g * 16 + (lane >> 4) * 8) * 2u);
            }
#pragma unroll
            for (int i = 0; i < 2; i++)
#pragma unroll
                for (int j = 0; j < 4; j++)
                    mma16816(acc[i][j], a[i], &b[j >> 1][(j & 1) * 2]);
        }
    }

    int lrow = lane >> 2, lcol = (lane & 3) * 2;
#pragma unroll
    for (int i = 0; i < 2; i++) {
#pragma unroll
        for (int j = 0; j < 4; j++) {
            int row = bm + wr * 32 + i * 16 + lrow;
            int col = bn + wc * 32 + j * 8 + lcol;
            if (HALF_OUT) {
                __half* C = (__half*)Cv;
                if (row < M)
                    *(__half2*)&C[(size_t)row * N + col] =
                        __floats2half2_rn(acc[i][j][0], acc[i][j][1]);
                if (row + 8 < M)
                    *(__half2*)&C[(size_t)(row + 8) * N + col] =
                        __floats2half2_rn(acc[i][j][2], acc[i][j][3]);
            } else {
                float* C = (float*)Cv;
                if (row < M)
                    *(float2*)&C[(size_t)row * N + col] =
                        make_float2(acc[i][j][0], acc[i][j][1]);
                if (row + 8 < M)
                    *(float2*)&C[(size_t)(row + 8) * N + col] =
                        make_float2(acc[i][j][2], acc[i][j][3]);
            }
        }
    }
}

// ---------------- GCN aggregation (fp16 gather, fp32 accum, split out) ----
__global__ void agg128_kernel(const __half* __restrict__ xw,
                              const float* __restrict__ bias) {
    int node = (blockIdx.x * blockDim.x + threadIdx.x) >> 5;
    int lane = threadIdx.x & 31;
    if (node >= NN) return;
    float di  = g_dinv[node];
    int   beg = g_rowptr[node], end = g_rowptr[node + 1];
    float4 acc = make_float4(0.f, 0.f, 0.f, 0.f);
    for (int base = beg; base < end; base += 32) {
        int m = end - base; if (m > 32) m = 32;
        int s = 0; float ds = 0.f;
        if (lane < m) { s = g_col[base + lane]; ds = g_dinv[s]; }
        int i = 0;
        for (; i + 8 <= m; i += 8) {
            int si[8]; float w[8]; uint2 xv[8];
#pragma unroll
            for (int j = 0; j < 8; j++) {
                si[j] = __shfl_sync(0xffffffffu, s,  i + j);
                w[j]  = __shfl_sync(0xffffffffu, ds, i + j);
            }
#pragma unroll
            for (int j = 0; j < 8; j++)
                xv[j] = *(const uint2*)(xw + (size_t)si[j] * 128 + lane * 4);
#pragma unroll
            for (int j = 0; j < 8; j++) {
                float2 lo = __half22float2(*(const __half2*)&xv[j].x);
                float2 hi = __half22float2(*(const __half2*)&xv[j].y);
                acc.x = fmaf(w[j], lo.x, acc.x);
                acc.y = fmaf(w[j], lo.y, acc.y);
                acc.z = fmaf(w[j], hi.x, acc.z);
                acc.w = fmaf(w[j], hi.y, acc.w);
            }
        }
        for (; i < m; i++) {
            int   si = __shfl_sync(0xffffffffu, s, i);
            float w  = __shfl_sync(0xffffffffu, ds, i);
            uint2 xv = *(const uint2*)(xw + (size_t)si * 128 + lane * 4);
            float2 lo = __half22float2(*(const __half2*)&xv.x);
            float2 hi = __half22float2(*(const __half2*)&xv.y);
            acc.x = fmaf(w, lo.x, acc.x); acc.y = fmaf(w, lo.y, acc.y);
            acc.z = fmaf(w, hi.x, acc.z); acc.w = fmaf(w, hi.y, acc.w);
        }
    }
    uint2 svp = *(const uint2*)(xw + (size_t)node * 128 + lane * 4);
    float2 slo = __half22float2(*(const __half2*)&svp.x);
    float2 shi = __half22float2(*(const __half2*)&svp.y);
    float4 b  = *(const float4*)(bias + lane * 4);
    float  d2 = di * di;
    float4 r;
    r.x = fmaxf(di * acc.x + d2 * slo.x + b.x, 0.f);
    r.y = fmaxf(di * acc.y + d2 * slo.y + b.y, 0.f);
    r.z = fmaxf(di * acc.z + d2 * shi.x + b.z, 0.f);
    r.w = fmaxf(di * acc.w + d2 * shi.y + b.w, 0.f);
    __half2 h01 = __floats2half2_rn(r.x, r.y);
    __half2 h23 = __floats2half2_rn(r.z, r.w);
    float2 f01 = __half22float2(h01), f23 = __half22float2(h23);
    __half2 l01 = __floats2half2_rn(r.x - f01.x, r.y - f01.y);
    __half2 l23 = __floats2half2_rn(r.z - f23.x, r.w - f23.y);
    __half2* hp = (__half2*)(g_hs + (size_t)node * 256 + lane * 4);
    hp[0] = h01; hp[1] = h23;
    __half2* lp = (__half2*)(g_hs + (size_t)node * 256 + 128 + lane * 4);
    lp[0] = l01; lp[1] = l23;
}

__global__ void agg64_kernel(const __half* __restrict__ xw,
                             const float* __restrict__ bias) {
    int node = (blockIdx.x * blockDim.x + threadIdx.x) >> 5;
    int lane = threadIdx.x & 31;
    if (node >= NN) return;
    float di  = g_dinv[node];
    int   beg = g_rowptr[node], end = g_rowptr[node + 1];
    float2 acc = make_float2(0.f, 0.f);
    for (int base = beg; base < end; base += 32) {
        int m = end - base; if (m > 32) m = 32;
        int s = 0; float ds = 0.f;
        if (lane < m) { s = g_col[base + lane]; ds = g_dinv[s]; }
        int i = 0;
        for (; i + 8 <= m; i += 8) {
            int si[8]; float w[8]; __half2 xv[8];
#pragma unroll
            for (int j = 0; j < 8; j++) {
                si[j] = __shfl_sync(0xffffffffu, s,  i + j);
                w[j]  = __shfl_sync(0xffffffffu, ds, i + j);
            }
#pragma unroll
            for (int j = 0; j < 8; j++)
                xv[j] = *(const __half2*)(xw + (size_t)si[j] * 64 + lane * 2);
#pragma unroll
            for (int j = 0; j < 8; j++) {
                float2 f = __half22float2(xv[j]);
                acc.x = fmaf(w[j], f.x, acc.x);
                acc.y = fmaf(w[j], f.y, acc.y);
            }
        }
        for (; i < m; i++) {
            int   si = __shfl_sync(0xffffffffu, s, i);
            float w  = __shfl_sync(0xffffffffu, ds, i);
            float2 f = __half22float2(*(const __half2*)(xw + (size_t)si * 64 + lane * 2));
            acc.x = fmaf(w, f.x, acc.x); acc.y = fmaf(w, f.y, acc.y);
        }
    }
    float2 sv = __half22float2(*(const __half2*)(xw + (size_t)node * 64 + lane * 2));
    float2 b  = *(const float2*)(bias + lane * 2);
    float  d2 = di * di;
    float rx = di * acc.x + d2 * sv.x + b.x;
    float ry = di * acc.y + d2 * sv.y + b.y;
    __half2 h = __floats2half2_rn(rx, ry);
    float2 f = __half22float2(h);
    __half2 l = __floats2half2_rn(rx - f.x, ry - f.y);
    *(__half2*)(g_zs + (size_t)node * 128 + lane * 2) = h;
    *(__half2*)(g_zs + (size_t)node * 128 + 64 + lane * 2) = l;
}

// ---------------- decode: warp per label edge, fp16 uv gather ----------------
__global__ void decode_kernel(const __half* __restrict__ uv,
                              const int* __restrict__ eli,
                              const float* __restrict__ b1,
                              const float* __restrict__ W2,
                              const float* __restrict__ b2,
                              float* __restrict__ out, int EL) {
    int e    = (blockIdx.x * blockDim.x + threadIdx.x) >> 5;
    int lane = threadIdx.x & 31;
    if (e >= EL) return;
    int s = eli[e];
    int d = eli[EL + e];
    const __half2* ps = (const __half2*)(uv + (size_t)s * 128);
    const __half2* pd = (const __half2*)(uv + (size_t)d * 128);
    float2 u_s = __half22float2(ps[lane]);
    float2 v_s = __half22float2(ps[32 + lane]);
    float2 u_d = __half22float2(pd[lane]);
    float2 v_d = __half22float2(pd[32 + lane]);
    float2 bb = ((const float2*)b1)[lane];
    float2 ww = ((const float2*)W2)[lane];
    float sum = 0.f, h;
    h = u_s.x + v_d.x + bb.x; sum = fmaf(fmaxf(h, 0.f), ww.x, sum);
    h = u_s.y + v_d.y + bb.y; sum = fmaf(fmaxf(h, 0.f), ww.y, sum);
    h = u_d.x + v_s.x + bb.x; sum = fmaf(fmaxf(h, 0.f), ww.x, sum);
    h = u_d.y + v_s.y + bb.y; sum = fmaf(fmaxf(h, 0.f), ww.y, sum);
#pragma unroll
    for (int o = 16; o; o >>= 1) sum += __shfl_xor_sync(0xffffffffu, sum, o);
    if (lane == 0) {
        float val = 0.5f * sum + b2[0];
        out[e]      = -val;
        out[EL + e] =  val;
    }
}

// ---------------- launch ----------------
extern "C" void kernel_launch(void* const* d_in, const int* in_sizes, int n_in,
                              void* d_out, int out_size) {
    const float* x   = (const float*)d_in[0];
    const int*   ei  = (const int*)d_in[1];
    const int*   eli = (const int*)d_in[2];
    const float* Wc1 = (const float*)d_in[3];
    const float* bc1 = (const float*)d_in[4];
    const float* Wc2 = (const float*)d_in[5];
    const float* bc2 = (const float*)d_in[6];
    const float* W1  = (const float*)d_in[7];
    const float* b1  = (const float*)d_in[8];
    const float* W2  = (const float*)d_in[9];
    const float* b2  = (const float*)d_in[10];
    float* out = (float*)d_out;

    int E  = in_sizes[1] / 2;
    int EL = in_sizes[2] / 2;

    void *p_xs, *p_hs, *p_zs, *p_xw16, *p_deg, *p_wc1c, *p_wc2c, *p_wuvc;
    cudaGetSymbolAddress(&p_xs,   g_xs);
    cudaGetSymbolAddress(&p_hs,   g_hs);
    cudaGetSymbolAddress(&p_zs,   g_zs);
    cudaGetSymbolAddress(&p_xw16, g_xw16);
    cudaGetSymbolAddress(&p_deg,  g_deg);
    cudaGetSymbolAddress(&p_wc1c, g_wc1c);
    cudaGetSymbolAddress(&p_wc2c, g_wc2c);
    cudaGetSymbolAddress(&p_wuvc, g_wuvc);

    static cudaStream_t s1 = nullptr;
    static cudaEvent_t  evFork = nullptr, evJoin = nullptr;
    if (s1 == nullptr) {
        cudaStreamCreateWithFlags(&s1, cudaStreamNonBlocking);
        cudaEventCreateWithFlags(&evFork, cudaEventDisableTiming);
        cudaEventCreateWithFlags(&evJoin, cudaEventDisableTiming);
    }

    int gy = (NN + 127) / 128;   // 391
    int E4 = E >> 2;

    // ---- fork: CSR chain on s1 ----
    cudaEventRecord(evFork, 0);
    cudaStreamWaitEvent(s1, evFork, 0);
    cudaMemsetAsync(p_deg, 0, NN * sizeof(int), s1);
    hist_kernel<<<(E4 + 255) / 256, 256, 0, s1>>>(ei + E, E);
    scan_partial_kernel<<<NB, 256, 0, s1>>>();
    scan_offsets_kernel<<<1, 256, 0, s1>>>(E);
    scan_final_kernel<<<NB, 256, 0, s1>>>();
    fill_kernel<<<(E4 + 255) / 256, 256, 0, s1>>>(ei, ei + E, E);
    cudaEventRecord(evJoin, s1);

    // main stream (concurrent): prep + GEMM1
    split_x_kernel<<<(NN * 32 + 255) / 256, 256>>>(x);
    build_cat_kernel<<<384, 128>>>(Wc1, (__half*)p_wc1c, 128, 128);
    build_cat_kernel<<<384, 64>>>(Wc2, (__half*)p_wc2c, 128, 64);
    build_wuvcat_kernel<<<192, 128>>>(W1);
    tcgemm_kernel<true><<<dim3(2, gy), 256>>>((const __half*)p_xs, (const __half*)p_wc1c,
                                              p_xw16, NN, 128, 128);

    // ---- join ----
    cudaStreamWaitEvent(0, evJoin, 0);

    agg128_kernel<<<(NN + 7) / 8, 256>>>((const __half*)p_xw16, bc1);
    tcgemm_kernel<true><<<dim3(1, gy), 256>>>((const __half*)p_hs, (const __half*)p_wc2c,
                                              p_xw16, NN, 64, 128);
    agg64_kernel<<<(NN + 7) / 8, 256>>>((const __half*)p_xw16, bc2);
    // uv (fp16) overwrites g_xw16 — hw contents dead after agg64 (same stream)
    tcgemm_kernel<true><<<dim3(2, gy), 256>>>((const __half*)p_zs, (const __half*)p_wuvc,
                                              p_xw16, NN, 128, 64);
    decode_kernel<<<(EL * 32 + 255) / 256, 256>>>((const __half*)p_xw16, eli, b1, W2, b2, out, EL);
}